// round 3
// baseline (speedup 1.0000x reference)
#include <cuda_runtime.h>
#include <math.h>

#define B_ 2
#define T_ 2048
#define C_ 2048
#define H_ 16
#define D_ 128
#define M_ (B_*T_)       /* 4096 */
#define NQKV_ (3*C_)     /* 6144 */

// Scratch (device globals: allocation-free per harness rules)
__device__ float g_qkv[(size_t)M_*NQKV_];      // ~100 MB [M, 3C]
__device__ float g_q[(size_t)B_*H_*T_*D_];     // [B,H,T,D]
__device__ float g_k[(size_t)B_*H_*T_*D_];
__device__ float g_v[(size_t)B_*H_*T_*D_];
__device__ float g_attn[(size_t)M_*C_];        // reference's transposed+reshaped layout

// ---------------------------------------------------------------------------
// Plain NT GEMM: Cmat[m,n] = sum_k A[m,k]*Bw[n,k].
// BM=BN=128, BK=16, 256 threads, 8x8 per-thread tile.
// ---------------------------------------------------------------------------
__global__ void __launch_bounds__(256)
gemm128(const float* __restrict__ A, const float* __restrict__ Bw,
        float* __restrict__ Cmat, int M, int N, int K)
{
    __shared__ float As[16][128];
    __shared__ float Bs[16][128];
    const int tid = threadIdx.x;
    const int m0 = blockIdx.y * 128;
    const int n0 = blockIdx.x * 128;
    const int ty = tid >> 4;          // 0..15
    const int tx = tid & 15;          // 0..15
    const int lr = tid >> 2;          // 0..63
    const int lc = (tid & 3) * 4;     // 0,4,8,12

    float acc[8][8];
#pragma unroll
    for (int i = 0; i < 8; ++i)
#pragma unroll
        for (int j = 0; j < 8; ++j) acc[i][j] = 0.0f;

    for (int k0 = 0; k0 < K; k0 += 16) {
        float4 a0 = *(const float4*)(A  + (size_t)(m0 + lr)      * K + k0 + lc);
        float4 a1 = *(const float4*)(A  + (size_t)(m0 + lr + 64) * K + k0 + lc);
        float4 b0 = *(const float4*)(Bw + (size_t)(n0 + lr)      * K + k0 + lc);
        float4 b1 = *(const float4*)(Bw + (size_t)(n0 + lr + 64) * K + k0 + lc);
        __syncthreads();
        As[lc+0][lr]    = a0.x; As[lc+1][lr]    = a0.y; As[lc+2][lr]    = a0.z; As[lc+3][lr]    = a0.w;
        As[lc+0][lr+64] = a1.x; As[lc+1][lr+64] = a1.y; As[lc+2][lr+64] = a1.z; As[lc+3][lr+64] = a1.w;
        Bs[lc+0][lr]    = b0.x; Bs[lc+1][lr]    = b0.y; Bs[lc+2][lr]    = b0.z; Bs[lc+3][lr]    = b0.w;
        Bs[lc+0][lr+64] = b1.x; Bs[lc+1][lr+64] = b1.y; Bs[lc+2][lr+64] = b1.z; Bs[lc+3][lr+64] = b1.w;
        __syncthreads();
#pragma unroll
        for (int kk = 0; kk < 16; ++kk) {
            float a[8], b[8];
#pragma unroll
            for (int i = 0; i < 8; ++i) a[i] = As[kk][ty*8 + i];
#pragma unroll
            for (int j = 0; j < 8; ++j) b[j] = Bs[kk][tx*8 + j];
#pragma unroll
            for (int i = 0; i < 8; ++i)
#pragma unroll
                for (int j = 0; j < 8; ++j) acc[i][j] += a[i] * b[j];
        }
    }
#pragma unroll
    for (int i = 0; i < 8; ++i) {
        float* crow = Cmat + (size_t)(m0 + ty*8 + i) * N + n0 + tx*8;
#pragma unroll
        for (int j = 0; j < 8; ++j) crow[j] = acc[i][j];
    }
}

// ---------------------------------------------------------------------------
// RoPE + reorganize: g_qkv [B*T, 3C] -> g_q/g_k/g_v [B,H,T,D], rope on q,k.
// One thread per (b,h,t,i), i in [0,64): handles the (i, i+64) pair.
// ---------------------------------------------------------------------------
__global__ void rope_reorg()
{
    const int idx = blockIdx.x * 256 + threadIdx.x;   // < 2^22
    const int i = idx & 63;
    const int t = (idx >> 6) & (T_ - 1);
    const int h = (idx >> 17) & (H_ - 1);
    const int b = idx >> 21;

    const size_t row = (size_t)(b*T_ + t) * NQKV_;
    const int    col = h*D_ + i;
    const float q1 = g_qkv[row + 0*C_ + col];
    const float q2 = g_qkv[row + 0*C_ + col + 64];
    const float k1 = g_qkv[row + 1*C_ + col];
    const float k2 = g_qkv[row + 1*C_ + col + 64];
    const float v1 = g_qkv[row + 2*C_ + col];
    const float v2 = g_qkv[row + 2*C_ + col + 64];

    const float mlt = (float)(-9.210340371976184 / 128.0);  // -ln(10000)/D
    const float ang = (float)t * expf((float)(2*i) * mlt);
    float s, c;
    sincosf(ang, &s, &c);

    const size_t off = ((size_t)(b*H_ + h) * T_ + t) * D_ + i;
    g_q[off]      = q1*c - q2*s;
    g_q[off + 64] = q2*c + q1*s;
    g_k[off]      = k1*c - k2*s;
    g_k[off + 64] = k2*c + k1*s;
    g_v[off]      = v1;
    g_v[off + 64] = v2;
}

// ---------------------------------------------------------------------------
// Causal flash attention, fp32. Block = (64-query tile, h, b), 256 threads.
// Epilogue writes the REFERENCE layout: transpose(0,2,1,3).reshape(B,T,C),
// i.e. attn[b,t,h,d] -> g_attn[b*T + 128*h + t/16, (t%16)*128 + d].
// ---------------------------------------------------------------------------
#define ATT_SMEM_FLOATS (64*129 + 64*129 + 64*128 + 64*65 + 3*64)

__global__ void __launch_bounds__(256)
attn_kernel()
{
    extern __shared__ float sm[];
    float* Qs   = sm;                  // [64][129]
    float* Ks   = Qs + 64*129;         // [64][129]
    float* Vs   = Ks + 64*129;         // [64][128]
    float* Ss   = Vs + 64*128;         // [64][65]
    float* m_s  = Ss + 64*65;
    float* l_s  = m_s + 64;
    float* sc_s = l_s + 64;

    const int tid = threadIdx.x;
    const int qt = blockIdx.x, h = blockIdx.y, b = blockIdx.z;
    const size_t head_off = (size_t)(b*H_ + h) * T_ * D_;
    const float* qb = g_q + head_off;
    const float* kb = g_k + head_off;
    const float* vb = g_v + head_off;
    const int q0 = qt * 64;

    // Load Q tile (stride 129)
    for (int i = tid; i < 64*32; i += 256) {
        const int r = i >> 5, c4 = (i & 31) * 4;
        const float* sp = qb + (size_t)(q0 + r)*D_ + c4;
        float* dp = Qs + r*129 + c4;
        dp[0] = sp[0]; dp[1] = sp[1]; dp[2] = sp[2]; dp[3] = sp[3];
    }
    if (tid < 64) { m_s[tid] = -INFINITY; l_s[tid] = 0.0f; }

    float acc[8][4];
#pragma unroll
    for (int j = 0; j < 8; ++j) { acc[j][0] = acc[j][1] = acc[j][2] = acc[j][3] = 0.0f; }

    const int rowg = tid >> 5;          // warp id -> owns rows rowg*8..+7 in PV
    const int col4 = (tid & 31) * 4;    // column group in D for PV
    const int qr = (tid >> 4) * 4;      // S micro-tile rows
    const int kc = (tid & 15) * 4;      // S micro-tile cols
    const float scl = 0.08838834764831845f;  // 1/sqrt(128)

    for (int kt = 0; kt <= qt; ++kt) {
        const int k0 = kt * 64;
        __syncthreads();   // prior iteration's PV reads of Vs/Ss complete
        for (int i = tid; i < 64*32; i += 256) {
            const int r = i >> 5, c4 = (i & 31) * 4;
            const float* sp = kb + (size_t)(k0 + r)*D_ + c4;
            float* dp = Ks + r*129 + c4;
            dp[0] = sp[0]; dp[1] = sp[1]; dp[2] = sp[2]; dp[3] = sp[3];
            const float* vp = vb + (size_t)(k0 + r)*D_ + c4;
            float* dv = Vs + r*128 + c4;
            dv[0] = vp[0]; dv[1] = vp[1]; dv[2] = vp[2]; dv[3] = vp[3];
        }
        __syncthreads();
        // S = Q K^T * scale  (4x4 micro-tile per thread)
        {
            float s[4][4];
#pragma unroll
            for (int i = 0; i < 4; ++i)
#pragma unroll
                for (int j = 0; j < 4; ++j) s[i][j] = 0.0f;
            for (int kk = 0; kk < 128; ++kk) {
                float a[4], bb[4];
#pragma unroll
                for (int i = 0; i < 4; ++i) a[i]  = Qs[(qr+i)*129 + kk];
#pragma unroll
                for (int j = 0; j < 4; ++j) bb[j] = Ks[(kc+j)*129 + kk];
#pragma unroll
                for (int i = 0; i < 4; ++i)
#pragma unroll
                    for (int j = 0; j < 4; ++j) s[i][j] += a[i] * bb[j];
            }
#pragma unroll
            for (int i = 0; i < 4; ++i)
#pragma unroll
                for (int j = 0; j < 4; ++j) Ss[(qr+i)*65 + kc + j] = s[i][j] * scl;
        }
        __syncthreads();
        // Online softmax: thread t owns row t
        if (tid < 64) {
            float* row = Ss + tid*65;
            const int kmax = (kt == qt) ? (tid + 1) : 64;   // causal
            const float m_old = m_s[tid];
            float mx = m_old;
            for (int c = 0; c < kmax; ++c) mx = fmaxf(mx, row[c]);
            float sum = 0.0f;
            for (int c = 0; c < 64; ++c) {
                const float p = (c < kmax) ? expf(row[c] - mx) : 0.0f;
                row[c] = p;
                sum += p;
            }
            const float sc = expf(m_old - mx);   // 0 on first tile
            m_s[tid]  = mx;
            l_s[tid]  = l_s[tid] * sc + sum;
            sc_s[tid] = sc;
        }
        __syncthreads();
        // O = O*sc + P V
#pragma unroll
        for (int j = 0; j < 8; ++j) {
            const float sc = sc_s[rowg*8 + j];
            acc[j][0] *= sc; acc[j][1] *= sc; acc[j][2] *= sc; acc[j][3] *= sc;
        }
        for (int kk = 0; kk < 64; ++kk) {
            const float* vrow = Vs + kk*128 + col4;
            const float v0 = vrow[0], v1 = vrow[1], v2 = vrow[2], v3 = vrow[3];
#pragma unroll
            for (int j = 0; j < 8; ++j) {
                const float p = Ss[(rowg*8 + j)*65 + kk];  // warp-uniform
                acc[j][0] += p*v0; acc[j][1] += p*v1;
                acc[j][2] += p*v2; acc[j][3] += p*v3;
            }
        }
    }
    __syncthreads();
#pragma unroll
    for (int j = 0; j < 8; ++j) {
        const int r = rowg*8 + j;
        const float inv = 1.0f / l_s[r];
        const int t = q0 + r;
        // Reference layout: row' = 128*h + t/16, col' = (t%16)*128 + d
        const int row2 = 128*h + (t >> 4);
        const int col2 = ((t & 15) << 7) + col4;
        float* op = g_attn + (size_t)(b*T_ + row2)*C_ + col2;
        op[0] = acc[j][0]*inv; op[1] = acc[j][1]*inv;
        op[2] = acc[j][2]*inv; op[3] = acc[j][3]*inv;
    }
}

// ---------------------------------------------------------------------------
extern "C" void kernel_launch(void* const* d_in, const int* in_sizes, int n_in,
                              void* d_out, int out_size)
{
    // Bind inputs by element count (robust to metadata ordering):
    const float* x = nullptr; const float* qkv_w = nullptr; const float* out_w = nullptr;
    for (int i = 0; i < n_in; ++i) {
        if      (in_sizes[i] == B_*T_*C_) x     = (const float*)d_in[i];
        else if (in_sizes[i] == 3*C_*C_)  qkv_w = (const float*)d_in[i];
        else if (in_sizes[i] == C_*C_)    out_w = (const float*)d_in[i];
    }
    if (!x)     x     = (const float*)d_in[0];
    if (!qkv_w) qkv_w = (const float*)d_in[1];
    if (!out_w) out_w = (const float*)d_in[2];
    float* out = (float*)d_out;

    float* qkv_ptr = nullptr; float* attn_ptr = nullptr;
    cudaGetSymbolAddress((void**)&qkv_ptr, g_qkv);
    cudaGetSymbolAddress((void**)&attn_ptr, g_attn);

    const size_t attn_smem = ATT_SMEM_FLOATS * sizeof(float);  // ~116 KB
    cudaFuncSetAttribute(attn_kernel, cudaFuncAttributeMaxDynamicSharedMemorySize,
                         (int)attn_smem);

    // 1) QKV projection: g_qkv = x @ qkv_w^T   [4096 x 6144]
    gemm128<<<dim3(NQKV_/128, M_/128), 256>>>(x, qkv_w, qkv_ptr, M_, NQKV_, C_);
    // 2) RoPE + reorganize to [B,H,T,D]
    rope_reorg<<<(B_*H_*T_*64)/256, 256>>>();
    // 3) Causal flash attention -> g_attn (reference's transposed layout)
    attn_kernel<<<dim3(T_/64, H_, B_), 256, attn_smem>>>();
    // 4) Output projection: out = g_attn @ out_w^T   [4096 x 2048]
    gemm128<<<dim3(C_/128, M_/128), 256>>>(attn_ptr, out_w, out, M_, C_, C_);
}

// round 4
// speedup vs baseline: 1.1009x; 1.1009x over previous
#include <cuda_runtime.h>
#include <math.h>

#define B_ 2
#define T_ 2048
#define C_ 2048
#define H_ 16
#define D_ 128
#define M_ (B_*T_)       /* 4096 */
#define NQKV_ (3*C_)     /* 6144 */

// Scratch (device globals: allocation-free per harness rules)
__device__ float g_qkv[(size_t)M_*NQKV_];      // [M, 3C]
__device__ float g_q [(size_t)B_*H_*T_*D_];    // [B,H,T,D]
__device__ float g_kt[(size_t)B_*H_*D_*T_];    // [B,H,D,T]  (d-major K)
__device__ float g_v [(size_t)B_*H_*T_*D_];    // [B,H,T,D]
__device__ float g_attn[(size_t)M_*C_];        // reference's transposed+reshaped layout

// ---------------------------------------------------------------------------
// Plain NT GEMM: Cmat[m,n] = sum_k A[m,k]*Bw[n,k].  (unchanged from R3)
// ---------------------------------------------------------------------------
__global__ void __launch_bounds__(256)
gemm128(const float* __restrict__ A, const float* __restrict__ Bw,
        float* __restrict__ Cmat, int M, int N, int K)
{
    __shared__ float As[16][128];
    __shared__ float Bs[16][128];
    const int tid = threadIdx.x;
    const int m0 = blockIdx.y * 128;
    const int n0 = blockIdx.x * 128;
    const int ty = tid >> 4;
    const int tx = tid & 15;
    const int lr = tid >> 2;
    const int lc = (tid & 3) * 4;

    float acc[8][8];
#pragma unroll
    for (int i = 0; i < 8; ++i)
#pragma unroll
        for (int j = 0; j < 8; ++j) acc[i][j] = 0.0f;

    for (int k0 = 0; k0 < K; k0 += 16) {
        float4 a0 = *(const float4*)(A  + (size_t)(m0 + lr)      * K + k0 + lc);
        float4 a1 = *(const float4*)(A  + (size_t)(m0 + lr + 64) * K + k0 + lc);
        float4 b0 = *(const float4*)(Bw + (size_t)(n0 + lr)      * K + k0 + lc);
        float4 b1 = *(const float4*)(Bw + (size_t)(n0 + lr + 64) * K + k0 + lc);
        __syncthreads();
        As[lc+0][lr]    = a0.x; As[lc+1][lr]    = a0.y; As[lc+2][lr]    = a0.z; As[lc+3][lr]    = a0.w;
        As[lc+0][lr+64] = a1.x; As[lc+1][lr+64] = a1.y; As[lc+2][lr+64] = a1.z; As[lc+3][lr+64] = a1.w;
        Bs[lc+0][lr]    = b0.x; Bs[lc+1][lr]    = b0.y; Bs[lc+2][lr]    = b0.z; Bs[lc+3][lr]    = b0.w;
        Bs[lc+0][lr+64] = b1.x; Bs[lc+1][lr+64] = b1.y; Bs[lc+2][lr+64] = b1.z; Bs[lc+3][lr+64] = b1.w;
        __syncthreads();
#pragma unroll
        for (int kk = 0; kk < 16; ++kk) {
            float a[8], b[8];
#pragma unroll
            for (int i = 0; i < 8; ++i) a[i] = As[kk][ty*8 + i];
#pragma unroll
            for (int j = 0; j < 8; ++j) b[j] = Bs[kk][tx*8 + j];
#pragma unroll
            for (int i = 0; i < 8; ++i)
#pragma unroll
                for (int j = 0; j < 8; ++j) acc[i][j] += a[i] * b[j];
        }
    }
#pragma unroll
    for (int i = 0; i < 8; ++i) {
        float* crow = Cmat + (size_t)(m0 + ty*8 + i) * N + n0 + tx*8;
#pragma unroll
        for (int j = 0; j < 8; ++j) crow[j] = acc[i][j];
    }
}

// ---------------------------------------------------------------------------
// RoPE + reorganize. Thread = (b,h,i,t4), t4 covers 4 consecutive t.
// q,v -> [B,H,T,D]; k -> [B,H,D,T] (d-major, consecutive t per thread keeps
// sector efficiency at 50%).
// ---------------------------------------------------------------------------
__global__ void rope_reorg()
{
    const int idx = blockIdx.x * 256 + threadIdx.x;   // < 2^20
    const int t4 = idx & 511;              // T/4
    const int i  = (idx >> 9) & 63;
    const int h  = (idx >> 15) & (H_ - 1);
    const int b  = idx >> 19;
    const int bh = b*H_ + h;
    const int col = h*D_ + i;

    const float mlt = (float)(-9.210340371976184 / 128.0);  // -ln(10000)/D
    const float div = expf((float)(2*i) * mlt);

#pragma unroll
    for (int u = 0; u < 4; ++u) {
        const int t = t4*4 + u;
        const size_t row = (size_t)(b*T_ + t) * NQKV_;
        const float q1 = g_qkv[row + 0*C_ + col];
        const float q2 = g_qkv[row + 0*C_ + col + 64];
        const float k1 = g_qkv[row + 1*C_ + col];
        const float k2 = g_qkv[row + 1*C_ + col + 64];
        const float v1 = g_qkv[row + 2*C_ + col];
        const float v2 = g_qkv[row + 2*C_ + col + 64];

        float s, c;
        sincosf((float)t * div, &s, &c);

        const size_t off = ((size_t)bh * T_ + t) * D_ + i;
        g_q[off]      = q1*c - q2*s;
        g_q[off + 64] = q2*c + q1*s;
        g_v[off]      = v1;
        g_v[off + 64] = v2;
        const size_t koff = ((size_t)bh * D_ + i) * T_ + t;
        g_kt[koff]            = k1*c - k2*s;
        g_kt[koff + 64*T_]    = k2*c + k1*s;
    }
}

// ---------------------------------------------------------------------------
// Causal flash attention, fp32, crossbar-optimized.
// Block = (64-query tile, h, b), 256 threads.
// K tile comes from g_kt as [128 d][64 n] -> S-phase b-frag is contiguous f4.
// Epilogue writes the reference layout (transpose(0,2,1,3).reshape).
// ---------------------------------------------------------------------------
#define QS_STRIDE 132
#define KT_STRIDE 68
#define SS_STRIDE 68
#define ATT_SMEM_FLOATS (64*QS_STRIDE + 128*KT_STRIDE + 64*128 + 64*SS_STRIDE + 3*64)

__global__ void __launch_bounds__(256, 1)
attn_kernel()
{
    extern __shared__ float sm[];
    float* Qs   = sm;                    // [64][132]
    float* Kts  = Qs  + 64*QS_STRIDE;    // [128][68]  (Kts[d][n])
    float* Vs   = Kts + 128*KT_STRIDE;   // [64][128]
    float* Ss   = Vs  + 64*128;          // [64][68]
    float* m_s  = Ss  + 64*SS_STRIDE;
    float* l_s  = m_s + 64;
    float* sc_s = l_s + 64;

    const int tid = threadIdx.x;
    const int qt = blockIdx.x, h = blockIdx.y, b = blockIdx.z;
    const float* qb  = g_q  + (size_t)(b*H_ + h) * T_ * D_;
    const float* ktb = g_kt + (size_t)(b*H_ + h) * D_ * T_;
    const float* vb  = g_v  + (size_t)(b*H_ + h) * T_ * D_;
    const int q0 = qt * 64;

    // Load Q tile [64][128] -> Qs stride 132
    for (int i = tid; i < 64*32; i += 256) {
        const int r = i >> 5, c4 = (i & 31) * 4;
        *(float4*)(Qs + r*QS_STRIDE + c4) =
            *(const float4*)(qb + (size_t)(q0 + r)*D_ + c4);
    }
    if (tid < 64) { m_s[tid] = -INFINITY; l_s[tid] = 0.0f; }

    float acc[8][4];
#pragma unroll
    for (int j = 0; j < 8; ++j) { acc[j][0] = acc[j][1] = acc[j][2] = acc[j][3] = 0.0f; }

    const int rowg = tid >> 5;           // warp id -> rows rowg*8..+7 in PV
    const int col4 = (tid & 31) * 4;     // D-column group in PV
    const int qr = (tid >> 4) * 4;       // S micro-tile rows
    const int kc = (tid & 15) * 4;       // S micro-tile cols
    const int sr = tid >> 2;             // softmax row
    const int sq = tid & 3;              // softmax lane-in-row
    const float scl = 0.08838834764831845f;  // 1/sqrt(128)

    for (int kt = 0; kt <= qt; ++kt) {
        const int k0 = kt * 64;
        __syncthreads();   // prior PV reads of Vs/Ss, prior S reads of Kts done
        // Load K tile (d-major) [128][64] and V tile [64][128]
        for (int i = tid; i < 128*16; i += 256) {
            const int d = i >> 4, c4 = (i & 15) * 4;
            *(float4*)(Kts + d*KT_STRIDE + c4) =
                *(const float4*)(ktb + (size_t)d*T_ + k0 + c4);
        }
        for (int i = tid; i < 64*32; i += 256) {
            const int r = i >> 5, c4 = (i & 31) * 4;
            *(float4*)(Vs + r*128 + c4) =
                *(const float4*)(vb + (size_t)(k0 + r)*D_ + c4);
        }
        __syncthreads();
        // S = Q K^T * scale  (4x4 micro-tile, f4-vectorized along kk)
        {
            float s[4][4];
#pragma unroll
            for (int i = 0; i < 4; ++i)
#pragma unroll
                for (int j = 0; j < 4; ++j) s[i][j] = 0.0f;
            for (int kk = 0; kk < 128; kk += 4) {
                float4 a0 = *(const float4*)(Qs + (qr+0)*QS_STRIDE + kk);
                float4 a1 = *(const float4*)(Qs + (qr+1)*QS_STRIDE + kk);
                float4 a2 = *(const float4*)(Qs + (qr+2)*QS_STRIDE + kk);
                float4 a3 = *(const float4*)(Qs + (qr+3)*QS_STRIDE + kk);
                float4 b0 = *(const float4*)(Kts + (kk+0)*KT_STRIDE + kc);
                float4 b1 = *(const float4*)(Kts + (kk+1)*KT_STRIDE + kc);
                float4 b2 = *(const float4*)(Kts + (kk+2)*KT_STRIDE + kc);
                float4 b3 = *(const float4*)(Kts + (kk+3)*KT_STRIDE + kc);
#define SSTEP(ai, si) \
    s[si][0] += ai.x*b0.x + ai.y*b1.x + ai.z*b2.x + ai.w*b3.x; \
    s[si][1] += ai.x*b0.y + ai.y*b1.y + ai.z*b2.y + ai.w*b3.y; \
    s[si][2] += ai.x*b0.z + ai.y*b1.z + ai.z*b2.z + ai.w*b3.z; \
    s[si][3] += ai.x*b0.w + ai.y*b1.w + ai.z*b2.w + ai.w*b3.w;
                SSTEP(a0, 0) SSTEP(a1, 1) SSTEP(a2, 2) SSTEP(a3, 3)
#undef SSTEP
            }
#pragma unroll
            for (int i = 0; i < 4; ++i) {
                float4 w = make_float4(s[i][0]*scl, s[i][1]*scl, s[i][2]*scl, s[i][3]*scl);
                *(float4*)(Ss + (qr+i)*SS_STRIDE + kc) = w;
            }
        }
        __syncthreads();
        // Online softmax: 4 lanes per row, shuffle reduce
        {
            float* row = Ss + sr*SS_STRIDE;
            const int kmax = (kt == qt) ? (sr + 1) : 64;
            const float m_old = m_s[sr];
            float mx = m_old;
#pragma unroll
            for (int c0 = 0; c0 < 16; ++c0) {
                const int c = sq*16 + c0;
                if (c < kmax) mx = fmaxf(mx, row[c]);
            }
            mx = fmaxf(mx, __shfl_xor_sync(0xffffffff, mx, 1));
            mx = fmaxf(mx, __shfl_xor_sync(0xffffffff, mx, 2));
            float sum = 0.0f;
#pragma unroll
            for (int c0 = 0; c0 < 16; ++c0) {
                const int c = sq*16 + c0;
                const float p = (c < kmax) ? __expf(row[c] - mx) : 0.0f;
                row[c] = p;
                sum += p;
            }
            sum += __shfl_xor_sync(0xffffffff, sum, 1);
            sum += __shfl_xor_sync(0xffffffff, sum, 2);
            if (sq == 0) {
                const float sc = __expf(m_old - mx);   // 0 on first tile
                m_s[sr]  = mx;
                l_s[sr]  = l_s[sr] * sc + sum;
                sc_s[sr] = sc;
            }
        }
        __syncthreads();
        // O = O*sc + P V   (V via conflict-free LDS.128, P via broadcast)
#pragma unroll
        for (int j = 0; j < 8; ++j) {
            const float sc = sc_s[rowg*8 + j];
            acc[j][0] *= sc; acc[j][1] *= sc; acc[j][2] *= sc; acc[j][3] *= sc;
        }
        for (int kk = 0; kk < 64; ++kk) {
            const float4 v = *(const float4*)(Vs + kk*128 + col4);
#pragma unroll
            for (int j = 0; j < 8; ++j) {
                const float p = Ss[(rowg*8 + j)*SS_STRIDE + kk];  // warp-uniform
                acc[j][0] += p*v.x; acc[j][1] += p*v.y;
                acc[j][2] += p*v.z; acc[j][3] += p*v.w;
            }
        }
    }
    __syncthreads();
#pragma unroll
    for (int j = 0; j < 8; ++j) {
        const int r = rowg*8 + j;
        const float inv = 1.0f / l_s[r];
        const int t = q0 + r;
        // Reference layout: row' = 128*h + t/16, col' = (t%16)*128 + d
        const int row2 = 128*h + (t >> 4);
        const int col2 = ((t & 15) << 7) + col4;
        float4 o = make_float4(acc[j][0]*inv, acc[j][1]*inv, acc[j][2]*inv, acc[j][3]*inv);
        *(float4*)(g_attn + (size_t)(b*T_ + row2)*C_ + col2) = o;
    }
}

// ---------------------------------------------------------------------------
extern "C" void kernel_launch(void* const* d_in, const int* in_sizes, int n_in,
                              void* d_out, int out_size)
{
    const float* x = nullptr; const float* qkv_w = nullptr; const float* out_w = nullptr;
    for (int i = 0; i < n_in; ++i) {
        if      (in_sizes[i] == B_*T_*C_) x     = (const float*)d_in[i];
        else if (in_sizes[i] == 3*C_*C_)  qkv_w = (const float*)d_in[i];
        else if (in_sizes[i] == C_*C_)    out_w = (const float*)d_in[i];
    }
    if (!x)     x     = (const float*)d_in[0];
    if (!qkv_w) qkv_w = (const float*)d_in[1];
    if (!out_w) out_w = (const float*)d_in[2];
    float* out = (float*)d_out;

    float* qkv_ptr = nullptr; float* attn_ptr = nullptr;
    cudaGetSymbolAddress((void**)&qkv_ptr, g_qkv);
    cudaGetSymbolAddress((void**)&attn_ptr, g_attn);

    const size_t attn_smem = ATT_SMEM_FLOATS * sizeof(float);  // ~119.6 KB
    cudaFuncSetAttribute(attn_kernel, cudaFuncAttributeMaxDynamicSharedMemorySize,
                         (int)attn_smem);

    // 1) QKV projection: g_qkv = x @ qkv_w^T   [4096 x 6144]
    gemm128<<<dim3(NQKV_/128, M_/128), 256>>>(x, qkv_w, qkv_ptr, M_, NQKV_, C_);
    // 2) RoPE + reorganize (q,v row-major; k d-major)
    rope_reorg<<<(B_*H_*64*(T_/4))/256, 256>>>();
    // 3) Causal flash attention -> g_attn (reference's transposed layout)
    attn_kernel<<<dim3(T_/64, H_, B_), 256, attn_smem>>>();
    // 4) Output projection: out = g_attn @ out_w^T   [4096 x 2048]
    gemm128<<<dim3(C_/128, M_/128), 256>>>(attn_ptr, out_w, out, M_, C_, C_);
}

// round 5
// speedup vs baseline: 1.1181x; 1.0156x over previous
#include <cuda_runtime.h>
#include <math.h>

#define B_ 2
#define T_ 2048
#define C_ 2048
#define H_ 16
#define D_ 128
#define M_ (B_*T_)       /* 4096 */
#define NQKV_ (3*C_)     /* 6144 */

// Scratch (device globals: allocation-free per harness rules)
__device__ float g_qkv[(size_t)M_*NQKV_];      // [M, 3C]
__device__ float g_q [(size_t)B_*H_*T_*D_];    // [B,H,T,D]
__device__ float g_kt[(size_t)B_*H_*D_*T_];    // [B,H,D,T]  (d-major K)
__device__ float g_v [(size_t)B_*H_*T_*D_];    // [B,H,T,D]
__device__ float g_attn[(size_t)M_*C_];        // reference's transposed+reshaped layout

// ---------------------------------------------------------------------------
// NT GEMM with register prefetch: Cmat[m,n] = sum_k A[m,k]*Bw[n,k].
// ---------------------------------------------------------------------------
__global__ void __launch_bounds__(256)
gemm128(const float* __restrict__ A, const float* __restrict__ Bw,
        float* __restrict__ Cmat, int M, int N, int K)
{
    __shared__ float As[16][128];
    __shared__ float Bs[16][128];
    const int tid = threadIdx.x;
    const int m0 = blockIdx.y * 128;
    const int n0 = blockIdx.x * 128;
    const int ty = tid >> 4;
    const int tx = tid & 15;
    const int lr = tid >> 2;
    const int lc = (tid & 3) * 4;

    const float* pa0 = A  + (size_t)(m0 + lr)      * K + lc;
    const float* pa1 = A  + (size_t)(m0 + lr + 64) * K + lc;
    const float* pb0 = Bw + (size_t)(n0 + lr)      * K + lc;
    const float* pb1 = Bw + (size_t)(n0 + lr + 64) * K + lc;

    float acc[8][8];
#pragma unroll
    for (int i = 0; i < 8; ++i)
#pragma unroll
        for (int j = 0; j < 8; ++j) acc[i][j] = 0.0f;

    float4 a0 = *(const float4*)(pa0);
    float4 a1 = *(const float4*)(pa1);
    float4 b0 = *(const float4*)(pb0);
    float4 b1 = *(const float4*)(pb1);

    for (int k0 = 0; k0 < K; k0 += 16) {
        __syncthreads();
        As[lc+0][lr]    = a0.x; As[lc+1][lr]    = a0.y; As[lc+2][lr]    = a0.z; As[lc+3][lr]    = a0.w;
        As[lc+0][lr+64] = a1.x; As[lc+1][lr+64] = a1.y; As[lc+2][lr+64] = a1.z; As[lc+3][lr+64] = a1.w;
        Bs[lc+0][lr]    = b0.x; Bs[lc+1][lr]    = b0.y; Bs[lc+2][lr]    = b0.z; Bs[lc+3][lr]    = b0.w;
        Bs[lc+0][lr+64] = b1.x; Bs[lc+1][lr+64] = b1.y; Bs[lc+2][lr+64] = b1.z; Bs[lc+3][lr+64] = b1.w;
        __syncthreads();
        if (k0 + 16 < K) {   // prefetch next slab; LDG latency overlaps compute
            a0 = *(const float4*)(pa0 + k0 + 16);
            a1 = *(const float4*)(pa1 + k0 + 16);
            b0 = *(const float4*)(pb0 + k0 + 16);
            b1 = *(const float4*)(pb1 + k0 + 16);
        }
#pragma unroll
        for (int kk = 0; kk < 16; ++kk) {
            float a[8], b[8];
#pragma unroll
            for (int i = 0; i < 8; ++i) a[i] = As[kk][ty*8 + i];
#pragma unroll
            for (int j = 0; j < 8; ++j) b[j] = Bs[kk][tx*8 + j];
#pragma unroll
            for (int i = 0; i < 8; ++i)
#pragma unroll
                for (int j = 0; j < 8; ++j) acc[i][j] += a[i] * b[j];
        }
    }
#pragma unroll
    for (int i = 0; i < 8; ++i) {
        float* crow = Cmat + (size_t)(m0 + ty*8 + i) * N + n0 + tx*8;
#pragma unroll
        for (int j = 0; j < 8; ++j) crow[j] = acc[i][j];
    }
}

// ---------------------------------------------------------------------------
// RoPE + reorganize (unchanged from R4).
// ---------------------------------------------------------------------------
__global__ void rope_reorg()
{
    const int idx = blockIdx.x * 256 + threadIdx.x;
    const int t4 = idx & 511;
    const int i  = (idx >> 9) & 63;
    const int h  = (idx >> 15) & (H_ - 1);
    const int b  = idx >> 19;
    const int bh = b*H_ + h;
    const int col = h*D_ + i;

    const float mlt = (float)(-9.210340371976184 / 128.0);
    const float div = expf((float)(2*i) * mlt);

#pragma unroll
    for (int u = 0; u < 4; ++u) {
        const int t = t4*4 + u;
        const size_t row = (size_t)(b*T_ + t) * NQKV_;
        const float q1 = g_qkv[row + 0*C_ + col];
        const float q2 = g_qkv[row + 0*C_ + col + 64];
        const float k1 = g_qkv[row + 1*C_ + col];
        const float k2 = g_qkv[row + 1*C_ + col + 64];
        const float v1 = g_qkv[row + 2*C_ + col];
        const float v2 = g_qkv[row + 2*C_ + col + 64];

        float s, c;
        sincosf((float)t * div, &s, &c);

        const size_t off = ((size_t)bh * T_ + t) * D_ + i;
        g_q[off]      = q1*c - q2*s;
        g_q[off + 64] = q2*c + q1*s;
        g_v[off]      = v1;
        g_v[off + 64] = v2;
        const size_t koff = ((size_t)bh * D_ + i) * T_ + t;
        g_kt[koff]         = k1*c - k2*s;
        g_kt[koff + 64*T_] = k2*c + k1*s;
    }
}

// ---------------------------------------------------------------------------
// Causal flash attention, fp32, 128-row Q tiles (FMA-bound design).
// Block = (128-q tile, h, b), 256 threads, 1 CTA/SM.
//   S phase : 8x4 micro-tile/thread, K from d-major g_kt (f4 frags both sides)
//   softmax : 2 lanes/row, shuffle reduce
//   PV phase: warp owns 16 rows; V f4 conflict-free; P f4 broadcast
// Epilogue writes the reference layout (transpose(0,2,1,3).reshape).
// ---------------------------------------------------------------------------
#define QS_STRIDE 132
#define KT_STRIDE 68
#define SS_STRIDE 68
#define ATT_SMEM_FLOATS (128*QS_STRIDE + 128*KT_STRIDE + 64*128 + 128*SS_STRIDE + 3*128)

__global__ void __launch_bounds__(256, 1)
attn_kernel()
{
    extern __shared__ float sm[];
    float* Qs   = sm;                     // [128][132]
    float* Kts  = Qs  + 128*QS_STRIDE;    // [128][68]   Kts[d][n]
    float* Vs   = Kts + 128*KT_STRIDE;    // [64][128]
    float* Ss   = Vs  + 64*128;           // [128][68]
    float* m_s  = Ss  + 128*SS_STRIDE;
    float* l_s  = m_s + 128;
    float* sc_s = l_s + 128;

    const int tid = threadIdx.x;
    const int qt = (gridDim.x - 1) - blockIdx.x;   // big blocks launch first
    const int h = blockIdx.y, b = blockIdx.z;
    const float* qb  = g_q  + (size_t)(b*H_ + h) * T_ * D_;
    const float* ktb = g_kt + (size_t)(b*H_ + h) * D_ * T_;
    const float* vb  = g_v  + (size_t)(b*H_ + h) * T_ * D_;
    const int q0 = qt * 128;

    // Load Q tile [128][128]
    for (int i = tid; i < 128*32; i += 256) {
        const int r = i >> 5, c4 = (i & 31) * 4;
        *(float4*)(Qs + r*QS_STRIDE + c4) =
            *(const float4*)(qb + (size_t)(q0 + r)*D_ + c4);
    }
    if (tid < 128) { m_s[tid] = -INFINITY; l_s[tid] = 0.0f; }

    float acc[16][4];
#pragma unroll
    for (int r = 0; r < 16; ++r)
#pragma unroll
        for (int j = 0; j < 4; ++j) acc[r][j] = 0.0f;

    const int qr = (tid >> 4) * 8;       // S micro-tile rows (8)
    const int kc = (tid & 15) * 4;       // S micro-tile cols (4)
    const int w  = tid >> 5;             // warp: PV rows w*16..+15
    const int lane4 = (tid & 31) * 4;    // PV D-column group
    const int sr = tid >> 1;             // softmax row
    const int sq = tid & 1;              // softmax half (32 cols)
    const float scl = 0.08838834764831845f;  // 1/sqrt(128)

    const int ntiles = 2*qt + 2;
    for (int kt = 0; kt < ntiles; ++kt) {
        const int k0 = kt * 64;
        __syncthreads();   // prior phase reads of Kts/Vs/Ss complete
        // Load K tile (d-major) [128][64] and V tile [64][128]
        for (int i = tid; i < 128*16; i += 256) {
            const int d = i >> 4, c4 = (i & 15) * 4;
            *(float4*)(Kts + d*KT_STRIDE + c4) =
                *(const float4*)(ktb + (size_t)d*T_ + k0 + c4);
        }
        for (int i = tid; i < 64*32; i += 256) {
            const int r = i >> 5, c4 = (i & 31) * 4;
            *(float4*)(Vs + r*128 + c4) =
                *(const float4*)(vb + (size_t)(k0 + r)*D_ + c4);
        }
        __syncthreads();
        // ---- S = Q K^T * scale (8x4 per thread) ----
        {
            float s[8][4];
#pragma unroll
            for (int i = 0; i < 8; ++i)
#pragma unroll
                for (int j = 0; j < 4; ++j) s[i][j] = 0.0f;
            for (int kk = 0; kk < 128; kk += 4) {
                float4 bb0 = *(const float4*)(Kts + (kk+0)*KT_STRIDE + kc);
                float4 bb1 = *(const float4*)(Kts + (kk+1)*KT_STRIDE + kc);
                float4 bb2 = *(const float4*)(Kts + (kk+2)*KT_STRIDE + kc);
                float4 bb3 = *(const float4*)(Kts + (kk+3)*KT_STRIDE + kc);
#pragma unroll
                for (int i = 0; i < 8; ++i) {
                    float4 a = *(const float4*)(Qs + (qr+i)*QS_STRIDE + kk);
                    s[i][0] += a.x*bb0.x + a.y*bb1.x + a.z*bb2.x + a.w*bb3.x;
                    s[i][1] += a.x*bb0.y + a.y*bb1.y + a.z*bb2.y + a.w*bb3.y;
                    s[i][2] += a.x*bb0.z + a.y*bb1.z + a.z*bb2.z + a.w*bb3.z;
                    s[i][3] += a.x*bb0.w + a.y*bb1.w + a.z*bb2.w + a.w*bb3.w;
                }
            }
#pragma unroll
            for (int i = 0; i < 8; ++i) {
                float4 wv = make_float4(s[i][0]*scl, s[i][1]*scl, s[i][2]*scl, s[i][3]*scl);
                *(float4*)(Ss + (qr+i)*SS_STRIDE + kc) = wv;
            }
        }
        __syncthreads();
        // ---- online softmax: 2 lanes per row ----
        {
            float* row = Ss + sr*SS_STRIDE;
            int kmax = q0 + sr - k0 + 1;            // causal bound for this row
            if (kmax > 64) kmax = 64;
            if (kmax < 0)  kmax = 0;
            const float m_old = m_s[sr];
            float mx = m_old;
#pragma unroll
            for (int g = 0; g < 8; ++g) {
                const int c = sq*32 + g*4;
                float4 v = *(const float4*)(row + c);
                if (c+0 < kmax) mx = fmaxf(mx, v.x);
                if (c+1 < kmax) mx = fmaxf(mx, v.y);
                if (c+2 < kmax) mx = fmaxf(mx, v.z);
                if (c+3 < kmax) mx = fmaxf(mx, v.w);
            }
            mx = fmaxf(mx, __shfl_xor_sync(0xffffffff, mx, 1));
            float sum = 0.0f;
#pragma unroll
            for (int g = 0; g < 8; ++g) {
                const int c = sq*32 + g*4;
                float4 v = *(const float4*)(row + c);
                v.x = (c+0 < kmax) ? __expf(v.x - mx) : 0.0f;
                v.y = (c+1 < kmax) ? __expf(v.y - mx) : 0.0f;
                v.z = (c+2 < kmax) ? __expf(v.z - mx) : 0.0f;
                v.w = (c+3 < kmax) ? __expf(v.w - mx) : 0.0f;
                *(float4*)(row + c) = v;
                sum += v.x + v.y + v.z + v.w;
            }
            sum += __shfl_xor_sync(0xffffffff, sum, 1);
            if (sq == 0) {
                const float sc = __expf(m_old - mx);   // 0 on first tile
                m_s[sr]  = mx;
                l_s[sr]  = l_s[sr] * sc + sum;
                sc_s[sr] = sc;
            }
        }
        __syncthreads();
        // ---- O = O*sc + P V ----
#pragma unroll
        for (int r = 0; r < 16; ++r) {
            const float sc = sc_s[w*16 + r];
            acc[r][0] *= sc; acc[r][1] *= sc; acc[r][2] *= sc; acc[r][3] *= sc;
        }
        for (int kk = 0; kk < 64; kk += 4) {
            const float4 v0 = *(const float4*)(Vs + (kk+0)*128 + lane4);
            const float4 v1 = *(const float4*)(Vs + (kk+1)*128 + lane4);
            const float4 v2 = *(const float4*)(Vs + (kk+2)*128 + lane4);
            const float4 v3 = *(const float4*)(Vs + (kk+3)*128 + lane4);
#pragma unroll
            for (int r = 0; r < 16; ++r) {
                const float4 p = *(const float4*)(Ss + (w*16 + r)*SS_STRIDE + kk);  // broadcast
                acc[r][0] += p.x*v0.x + p.y*v1.x + p.z*v2.x + p.w*v3.x;
                acc[r][1] += p.x*v0.y + p.y*v1.y + p.z*v2.y + p.w*v3.y;
                acc[r][2] += p.x*v0.z + p.y*v1.z + p.z*v2.z + p.w*v3.z;
                acc[r][3] += p.x*v0.w + p.y*v1.w + p.z*v2.w + p.w*v3.w;
            }
        }
    }
    __syncthreads();
#pragma unroll
    for (int r = 0; r < 16; ++r) {
        const int rowq = w*16 + r;
        const float inv = 1.0f / l_s[rowq];
        const int t = q0 + rowq;
        // Reference layout: row' = 128*h + t/16, col' = (t%16)*128 + d
        const int row2 = 128*h + (t >> 4);
        const int col2 = ((t & 15) << 7) + lane4;
        float4 o = make_float4(acc[r][0]*inv, acc[r][1]*inv, acc[r][2]*inv, acc[r][3]*inv);
        *(float4*)(g_attn + (size_t)(b*T_ + row2)*C_ + col2) = o;
    }
}

// ---------------------------------------------------------------------------
extern "C" void kernel_launch(void* const* d_in, const int* in_sizes, int n_in,
                              void* d_out, int out_size)
{
    const float* x = nullptr; const float* qkv_w = nullptr; const float* out_w = nullptr;
    for (int i = 0; i < n_in; ++i) {
        if      (in_sizes[i] == B_*T_*C_) x     = (const float*)d_in[i];
        else if (in_sizes[i] == 3*C_*C_)  qkv_w = (const float*)d_in[i];
        else if (in_sizes[i] == C_*C_)    out_w = (const float*)d_in[i];
    }
    if (!x)     x     = (const float*)d_in[0];
    if (!qkv_w) qkv_w = (const float*)d_in[1];
    if (!out_w) out_w = (const float*)d_in[2];
    float* out = (float*)d_out;

    float* qkv_ptr = nullptr; float* attn_ptr = nullptr;
    cudaGetSymbolAddress((void**)&qkv_ptr, g_qkv);
    cudaGetSymbolAddress((void**)&attn_ptr, g_attn);

    const size_t attn_smem = ATT_SMEM_FLOATS * sizeof(float);  // ~171.5 KB
    cudaFuncSetAttribute(attn_kernel, cudaFuncAttributeMaxDynamicSharedMemorySize,
                         (int)attn_smem);

    // 1) QKV projection: g_qkv = x @ qkv_w^T   [4096 x 6144]
    gemm128<<<dim3(NQKV_/128, M_/128), 256>>>(x, qkv_w, qkv_ptr, M_, NQKV_, C_);
    // 2) RoPE + reorganize (q,v row-major; k d-major)
    rope_reorg<<<(B_*H_*64*(T_/4))/256, 256>>>();
    // 3) Causal flash attention -> g_attn (reference's transposed layout)
    attn_kernel<<<dim3(T_/128, H_, B_), 256, attn_smem>>>();
    // 4) Output projection: out = g_attn @ out_w^T   [4096 x 2048]
    gemm128<<<dim3(C_/128, M_/128), 256>>>(attn_ptr, out_w, out, M_, C_, C_);
}

// round 7
// speedup vs baseline: 1.8509x; 1.6554x over previous
#include <cuda_runtime.h>
#include <cuda_bf16.h>
#include <math.h>
#include <stdint.h>

#define B_ 2
#define T_ 2048
#define C_ 2048
#define H_ 16
#define D_ 128
#define M_ 4096
#define NQKV_ 6144
#define K_ 2048
#define NCHUNK 32      /* K_/64 */

// ---------------- scratch (device globals: allocation-free) ----------------
__device__ float g_qkv[(size_t)M_*NQKV_];
__device__ float g_q [(size_t)B_*H_*T_*D_];
__device__ float g_kt[(size_t)B_*H_*D_*T_];
__device__ float g_v [(size_t)B_*H_*T_*D_];
__device__ float g_attn[(size_t)M_*C_];
__device__ __nv_bfloat16 g_xh[(size_t)M_*C_],    g_xl[(size_t)M_*C_];
__device__ __nv_bfloat16 g_wh[(size_t)NQKV_*C_], g_wl[(size_t)NQKV_*C_];
__device__ __nv_bfloat16 g_oh[(size_t)C_*C_],    g_ol[(size_t)C_*C_];
__device__ __nv_bfloat16 g_ah[(size_t)M_*C_],    g_al[(size_t)M_*C_];

extern __shared__ __align__(16) char dyn_smem[];

// ---------------- sm_80-class primitives (legal on plain sm_103) -----------
__device__ __forceinline__ uint32_t smem_u32(const void* p) {
    uint32_t a;
    asm("{ .reg .u64 t; cvta.to.shared.u64 t, %1; cvt.u32.u64 %0, t; }"
        : "=r"(a) : "l"(p));
    return a;
}
__device__ __forceinline__ void cp16(uint32_t dst, const void* src) {
    asm volatile("cp.async.cg.shared.global [%0], [%1], 16;"
                 :: "r"(dst), "l"(src) : "memory");
}
__device__ __forceinline__ void cp_commit() {
    asm volatile("cp.async.commit_group;" ::: "memory");
}
__device__ __forceinline__ void cp_wait0() {
    asm volatile("cp.async.wait_group 0;" ::: "memory");
}
__device__ __forceinline__ void ldsm_x4(uint32_t* r, uint32_t addr) {
    asm volatile("ldmatrix.sync.aligned.m8n8.x4.shared.b16 {%0,%1,%2,%3}, [%4];"
                 : "=r"(r[0]), "=r"(r[1]), "=r"(r[2]), "=r"(r[3]) : "r"(addr));
}
__device__ __forceinline__ void mma16816(float* c, const uint32_t* a, const uint32_t* b) {
    asm volatile(
        "mma.sync.aligned.m16n8k16.row.col.f32.bf16.bf16.f32 "
        "{%0,%1,%2,%3}, {%4,%5,%6,%7}, {%8,%9}, {%0,%1,%2,%3};"
        : "+f"(c[0]), "+f"(c[1]), "+f"(c[2]), "+f"(c[3])
        : "r"(a[0]), "r"(a[1]), "r"(a[2]), "r"(a[3]), "r"(b[0]), "r"(b[1]));
}
// SW128 swizzled address inside a [rows][64 bf16] tile (128B rows)
__device__ __forceinline__ uint32_t swz(uint32_t tile_base, int row, int col2 /*bytes*/) {
    return tile_base + ((uint32_t)row << 7) + ((uint32_t)col2 ^ (((uint32_t)row & 7u) << 4));
}

// ---------------------------------------------------------------------------
// fp32 -> (bf16 hi, bf16 lo) split, 4 elements per thread.
// ---------------------------------------------------------------------------
__global__ void __launch_bounds__(256)
split_bf16(const float* __restrict__ src, __nv_bfloat16* __restrict__ hi,
           __nv_bfloat16* __restrict__ lo, int n4)
{
    const int i = blockIdx.x*256 + threadIdx.x;
    if (i >= n4) return;
    const float4 v = ((const float4*)src)[i];
    float f[4] = {v.x, v.y, v.z, v.w};
    __nv_bfloat16 h[4], l[4];
#pragma unroll
    for (int j = 0; j < 4; ++j) {
        h[j] = __float2bfloat16_rn(f[j]);
        l[j] = __float2bfloat16_rn(f[j] - __bfloat162float(h[j]));
    }
    ((__nv_bfloat162*)hi)[i*2+0] = __halves2bfloat162(h[0], h[1]);
    ((__nv_bfloat162*)hi)[i*2+1] = __halves2bfloat162(h[2], h[3]);
    ((__nv_bfloat162*)lo)[i*2+0] = __halves2bfloat162(l[0], l[1]);
    ((__nv_bfloat162*)lo)[i*2+1] = __halves2bfloat162(l[2], l[3]);
}

// ---------------------------------------------------------------------------
// HMMA bf16 3-split NT GEMM: C[m,n] = sum_k A[m,k]*B[n,k], fp32 accum.
// CTA 128x128, BK=64 (SW128 swizzle), 8 warps (warp tile 64x32),
// cp.async double buffer. grid = (N/128, M/128), 256 threads.
// ---------------------------------------------------------------------------
#define TCOFF(buf, t) ((uint32_t)(((buf)*4 + (t)) * 16384))
#define TC_SMEM (8*16384)   /* 128 KB */

__device__ __forceinline__ void load_tile_async(uint32_t tile_base,
        const __nv_bfloat16* __restrict__ src, int row0, int k0, int tid)
{
    const char* base = (const char*)(src + (size_t)row0 * K_ + k0);
#pragma unroll
    for (int u = 0; u < 4; ++u) {
        const int c = tid*4 + u;                  // 0..1023
        const int row = c >> 3, col16 = (c & 7) * 16;
        uint32_t o = (uint32_t)(row*128 + col16);
        o ^= ((o >> 3) & 0x70);                   // SW128 swizzle
        cp16(tile_base + o, base + (size_t)row * (K_*2) + col16);
    }
}

__global__ void __launch_bounds__(256, 1)
tc_gemm(const __nv_bfloat16* __restrict__ Ah, const __nv_bfloat16* __restrict__ Al,
        const __nv_bfloat16* __restrict__ Bh, const __nv_bfloat16* __restrict__ Bl,
        float* __restrict__ Cout, int N)
{
    const uint32_t sbase = smem_u32(dyn_smem);
    const int tid = threadIdx.x, wid = tid >> 5, lane = tid & 31;
    const int wy = wid >> 2, wx = wid & 3;        // 2x4 warp grid
    const int m0 = blockIdx.y * 128, n0 = blockIdx.x * 128;
    const int r = lane & 7, g = lane >> 3;

    float acc[4][4][4];
#pragma unroll
    for (int i = 0; i < 4; ++i)
#pragma unroll
        for (int j = 0; j < 4; ++j)
#pragma unroll
            for (int e = 0; e < 4; ++e) acc[i][j][e] = 0.0f;

    // prologue: chunk 0 -> buf 0
    load_tile_async(sbase + TCOFF(0,0), Ah, m0, 0, tid);
    load_tile_async(sbase + TCOFF(0,1), Al, m0, 0, tid);
    load_tile_async(sbase + TCOFF(0,2), Bh, n0, 0, tid);
    load_tile_async(sbase + TCOFF(0,3), Bl, n0, 0, tid);
    cp_commit(); cp_wait0();
    __syncthreads();

    for (int chunk = 0; chunk < NCHUNK; ++chunk) {
        const int buf = chunk & 1;
        if (chunk + 1 < NCHUNK) {                 // prefetch next chunk
            const int k0n = (chunk + 1) * 64;
            load_tile_async(sbase + TCOFF(buf^1,0), Ah, m0, k0n, tid);
            load_tile_async(sbase + TCOFF(buf^1,1), Al, m0, k0n, tid);
            load_tile_async(sbase + TCOFF(buf^1,2), Bh, n0, k0n, tid);
            load_tile_async(sbase + TCOFF(buf^1,3), Bl, n0, k0n, tid);
            cp_commit();
        }
        const uint32_t aH = sbase + TCOFF(buf,0), aL = sbase + TCOFF(buf,1);
        const uint32_t bH = sbase + TCOFF(buf,2), bL = sbase + TCOFF(buf,3);
#pragma unroll
        for (int ks = 0; ks < 4; ++ks) {
            uint32_t ah[4][4], alr[4][4], bh[4][2], blr[4][2];
            const int colA = ks*32 + (g>>1)*16;   // bytes within 128B row
            const int colB = ks*32 + (g&1)*16;
#pragma unroll
            for (int i = 0; i < 4; ++i) {
                const int row = wy*64 + i*16 + r + (g&1)*8;
                ldsm_x4(ah[i],  swz(aH, row, colA));
                ldsm_x4(alr[i], swz(aL, row, colA));
            }
#pragma unroll
            for (int jj = 0; jj < 2; ++jj) {
                const int row = wx*32 + jj*16 + r + (g>>1)*8;
                uint32_t t[4];
                ldsm_x4(t, swz(bH, row, colB));
                bh[jj*2][0]=t[0]; bh[jj*2][1]=t[1];
                bh[jj*2+1][0]=t[2]; bh[jj*2+1][1]=t[3];
                ldsm_x4(t, swz(bL, row, colB));
                blr[jj*2][0]=t[0]; blr[jj*2][1]=t[1];
                blr[jj*2+1][0]=t[2]; blr[jj*2+1][1]=t[3];
            }
#pragma unroll
            for (int i = 0; i < 4; ++i)
#pragma unroll
                for (int j = 0; j < 4; ++j) {
                    mma16816(acc[i][j], ah[i],  bh[j]);   // hi*hi
                    mma16816(acc[i][j], ah[i],  blr[j]);  // hi*lo
                    mma16816(acc[i][j], alr[i], bh[j]);   // lo*hi
                }
        }
        if (chunk + 1 < NCHUNK) cp_wait0();
        __syncthreads();
    }

    // epilogue: c-frag thread mapping: rows lane>>2 (+8), cols (lane&3)*2
#pragma unroll
    for (int i = 0; i < 4; ++i) {
        const int rm = m0 + wy*64 + i*16 + (lane >> 2);
#pragma unroll
        for (int j = 0; j < 4; ++j) {
            const int cn = n0 + wx*32 + j*8 + (lane & 3)*2;
            *(float2*)&Cout[(size_t)rm*N + cn]       = make_float2(acc[i][j][0], acc[i][j][1]);
            *(float2*)&Cout[(size_t)(rm+8)*N + cn]   = make_float2(acc[i][j][2], acc[i][j][3]);
        }
    }
}

// ---------------------------------------------------------------------------
// RoPE + reorganize (unchanged, last passed R5).
// ---------------------------------------------------------------------------
__global__ void rope_reorg()
{
    const int idx = blockIdx.x * 256 + threadIdx.x;
    const int t4 = idx & 511;
    const int i  = (idx >> 9) & 63;
    const int h  = (idx >> 15) & (H_ - 1);
    const int b  = idx >> 19;
    const int bh = b*H_ + h;
    const int col = h*D_ + i;

    const float mlt = (float)(-9.210340371976184 / 128.0);
    const float div = expf((float)(2*i) * mlt);

#pragma unroll
    for (int u = 0; u < 4; ++u) {
        const int t = t4*4 + u;
        const size_t row = (size_t)(b*T_ + t) * NQKV_;
        const float q1 = g_qkv[row + 0*C_ + col];
        const float q2 = g_qkv[row + 0*C_ + col + 64];
        const float k1 = g_qkv[row + 1*C_ + col];
        const float k2 = g_qkv[row + 1*C_ + col + 64];
        const float v1 = g_qkv[row + 2*C_ + col];
        const float v2 = g_qkv[row + 2*C_ + col + 64];

        float s, c;
        sincosf((float)t * div, &s, &c);

        const size_t off = ((size_t)bh * T_ + t) * D_ + i;
        g_q[off]      = q1*c - q2*s;
        g_q[off + 64] = q2*c + q1*s;
        g_v[off]      = v1;
        g_v[off + 64] = v2;
        const size_t koff = ((size_t)bh * D_ + i) * T_ + t;
        g_kt[koff]         = k1*c - k2*s;
        g_kt[koff + 64*T_] = k2*c + k1*s;
    }
}

// ---------------------------------------------------------------------------
// Causal flash attention, fp32, 128-row Q tiles (unchanged, last passed R5).
// ---------------------------------------------------------------------------
#define QS_STRIDE 132
#define KT_STRIDE 68
#define SS_STRIDE 68
#define ATT_SMEM_FLOATS (128*QS_STRIDE + 128*KT_STRIDE + 64*128 + 128*SS_STRIDE + 3*128)

__global__ void __launch_bounds__(256, 1)
attn_kernel()
{
    float* sm   = (float*)dyn_smem;
    float* Qs   = sm;
    float* Kts  = Qs  + 128*QS_STRIDE;
    float* Vs   = Kts + 128*KT_STRIDE;
    float* Ss   = Vs  + 64*128;
    float* m_s  = Ss  + 128*SS_STRIDE;
    float* l_s  = m_s + 128;
    float* sc_s = l_s + 128;

    const int tid = threadIdx.x;
    const int qt = (gridDim.x - 1) - blockIdx.x;
    const int h = blockIdx.y, b = blockIdx.z;
    const float* qb  = g_q  + (size_t)(b*H_ + h) * T_ * D_;
    const float* ktb = g_kt + (size_t)(b*H_ + h) * D_ * T_;
    const float* vb  = g_v  + (size_t)(b*H_ + h) * T_ * D_;
    const int q0 = qt * 128;

    for (int i = tid; i < 128*32; i += 256) {
        const int r = i >> 5, c4 = (i & 31) * 4;
        *(float4*)(Qs + r*QS_STRIDE + c4) =
            *(const float4*)(qb + (size_t)(q0 + r)*D_ + c4);
    }
    if (tid < 128) { m_s[tid] = -INFINITY; l_s[tid] = 0.0f; }

    float acc[16][4];
#pragma unroll
    for (int r = 0; r < 16; ++r)
#pragma unroll
        for (int j = 0; j < 4; ++j) acc[r][j] = 0.0f;

    const int qr = (tid >> 4) * 8;
    const int kc = (tid & 15) * 4;
    const int w  = tid >> 5;
    const int lane4 = (tid & 31) * 4;
    const int sr = tid >> 1;
    const int sq = tid & 1;
    const float scl = 0.08838834764831845f;

    const int ntiles = 2*qt + 2;
    for (int kt = 0; kt < ntiles; ++kt) {
        const int k0 = kt * 64;
        __syncthreads();
        for (int i = tid; i < 128*16; i += 256) {
            const int d = i >> 4, c4 = (i & 15) * 4;
            *(float4*)(Kts + d*KT_STRIDE + c4) =
                *(const float4*)(ktb + (size_t)d*T_ + k0 + c4);
        }
        for (int i = tid; i < 64*32; i += 256) {
            const int r = i >> 5, c4 = (i & 31) * 4;
            *(float4*)(Vs + r*128 + c4) =
                *(const float4*)(vb + (size_t)(k0 + r)*D_ + c4);
        }
        __syncthreads();
        {
            float s[8][4];
#pragma unroll
            for (int i = 0; i < 8; ++i)
#pragma unroll
                for (int j = 0; j < 4; ++j) s[i][j] = 0.0f;
            for (int kk = 0; kk < 128; kk += 4) {
                float4 bb0 = *(const float4*)(Kts + (kk+0)*KT_STRIDE + kc);
                float4 bb1 = *(const float4*)(Kts + (kk+1)*KT_STRIDE + kc);
                float4 bb2 = *(const float4*)(Kts + (kk+2)*KT_STRIDE + kc);
                float4 bb3 = *(const float4*)(Kts + (kk+3)*KT_STRIDE + kc);
#pragma unroll
                for (int i = 0; i < 8; ++i) {
                    float4 a = *(const float4*)(Qs + (qr+i)*QS_STRIDE + kk);
                    s[i][0] += a.x*bb0.x + a.y*bb1.x + a.z*bb2.x + a.w*bb3.x;
                    s[i][1] += a.x*bb0.y + a.y*bb1.y + a.z*bb2.y + a.w*bb3.y;
                    s[i][2] += a.x*bb0.z + a.y*bb1.z + a.z*bb2.z + a.w*bb3.z;
                    s[i][3] += a.x*bb0.w + a.y*bb1.w + a.z*bb2.w + a.w*bb3.w;
                }
            }
#pragma unroll
            for (int i = 0; i < 8; ++i) {
                float4 wv = make_float4(s[i][0]*scl, s[i][1]*scl, s[i][2]*scl, s[i][3]*scl);
                *(float4*)(Ss + (qr+i)*SS_STRIDE + kc) = wv;
            }
        }
        __syncthreads();
        {
            float* row = Ss + sr*SS_STRIDE;
            int kmax = q0 + sr - k0 + 1;
            if (kmax > 64) kmax = 64;
            if (kmax < 0)  kmax = 0;
            const float m_old = m_s[sr];
            float mx = m_old;
#pragma unroll
            for (int g = 0; g < 8; ++g) {
                const int c = sq*32 + g*4;
                float4 v = *(const float4*)(row + c);
                if (c+0 < kmax) mx = fmaxf(mx, v.x);
                if (c+1 < kmax) mx = fmaxf(mx, v.y);
                if (c+2 < kmax) mx = fmaxf(mx, v.z);
                if (c+3 < kmax) mx = fmaxf(mx, v.w);
            }
            mx = fmaxf(mx, __shfl_xor_sync(0xffffffff, mx, 1));
            float sum = 0.0f;
#pragma unroll
            for (int g = 0; g < 8; ++g) {
                const int c = sq*32 + g*4;
                float4 v = *(const float4*)(row + c);
                v.x = (c+0 < kmax) ? __expf(v.x - mx) : 0.0f;
                v.y = (c+1 < kmax) ? __expf(v.y - mx) : 0.0f;
                v.z = (c+2 < kmax) ? __expf(v.z - mx) : 0.0f;
                v.w = (c+3 < kmax) ? __expf(v.w - mx) : 0.0f;
                *(float4*)(row + c) = v;
                sum += v.x + v.y + v.z + v.w;
            }
            sum += __shfl_xor_sync(0xffffffff, sum, 1);
            if (sq == 0) {
                const float sc = __expf(m_old - mx);
                m_s[sr]  = mx;
                l_s[sr]  = l_s[sr] * sc + sum;
                sc_s[sr] = sc;
            }
        }
        __syncthreads();
#pragma unroll
        for (int r = 0; r < 16; ++r) {
            const float sc = sc_s[w*16 + r];
            acc[r][0] *= sc; acc[r][1] *= sc; acc[r][2] *= sc; acc[r][3] *= sc;
        }
        for (int kk = 0; kk < 64; kk += 4) {
            const float4 v0 = *(const float4*)(Vs + (kk+0)*128 + lane4);
            const float4 v1 = *(const float4*)(Vs + (kk+1)*128 + lane4);
            const float4 v2 = *(const float4*)(Vs + (kk+2)*128 + lane4);
            const float4 v3 = *(const float4*)(Vs + (kk+3)*128 + lane4);
#pragma unroll
            for (int r = 0; r < 16; ++r) {
                const float4 p = *(const float4*)(Ss + (w*16 + r)*SS_STRIDE + kk);
                acc[r][0] += p.x*v0.x + p.y*v1.x + p.z*v2.x + p.w*v3.x;
                acc[r][1] += p.x*v0.y + p.y*v1.y + p.z*v2.y + p.w*v3.y;
                acc[r][2] += p.x*v0.z + p.y*v1.z + p.z*v2.z + p.w*v3.z;
                acc[r][3] += p.x*v0.w + p.y*v1.w + p.z*v2.w + p.w*v3.w;
            }
        }
    }
    __syncthreads();
#pragma unroll
    for (int r = 0; r < 16; ++r) {
        const int rowq = w*16 + r;
        const float inv = 1.0f / l_s[rowq];
        const int t = q0 + rowq;
        const int row2 = 128*h + (t >> 4);
        const int col2 = ((t & 15) << 7) + lane4;
        float4 o = make_float4(acc[r][0]*inv, acc[r][1]*inv, acc[r][2]*inv, acc[r][3]*inv);
        *(float4*)(g_attn + (size_t)(b*T_ + row2)*C_ + col2) = o;
    }
}

// ---------------------------------------------------------------------------
extern "C" void kernel_launch(void* const* d_in, const int* in_sizes, int n_in,
                              void* d_out, int out_size)
{
    const float* x = nullptr; const float* qkv_w = nullptr; const float* out_w = nullptr;
    for (int i = 0; i < n_in; ++i) {
        if      (in_sizes[i] == B_*T_*C_) x     = (const float*)d_in[i];
        else if (in_sizes[i] == 3*C_*C_)  qkv_w = (const float*)d_in[i];
        else if (in_sizes[i] == C_*C_)    out_w = (const float*)d_in[i];
    }
    if (!x)     x     = (const float*)d_in[0];
    if (!qkv_w) qkv_w = (const float*)d_in[1];
    if (!out_w) out_w = (const float*)d_in[2];
    float* out = (float*)d_out;

    float *qkv_ptr, *attn_ptr;
    __nv_bfloat16 *xh, *xl, *wh, *wl, *oh, *ol, *ah, *al;
    cudaGetSymbolAddress((void**)&qkv_ptr,  g_qkv);
    cudaGetSymbolAddress((void**)&attn_ptr, g_attn);
    cudaGetSymbolAddress((void**)&xh, g_xh); cudaGetSymbolAddress((void**)&xl, g_xl);
    cudaGetSymbolAddress((void**)&wh, g_wh); cudaGetSymbolAddress((void**)&wl, g_wl);
    cudaGetSymbolAddress((void**)&oh, g_oh); cudaGetSymbolAddress((void**)&ol, g_ol);
    cudaGetSymbolAddress((void**)&ah, g_ah); cudaGetSymbolAddress((void**)&al, g_al);

    const size_t attn_smem = ATT_SMEM_FLOATS * sizeof(float);
    cudaFuncSetAttribute(attn_kernel, cudaFuncAttributeMaxDynamicSharedMemorySize,
                         (int)attn_smem);
    cudaFuncSetAttribute(tc_gemm, cudaFuncAttributeMaxDynamicSharedMemorySize, TC_SMEM);

    // 1) fp32 -> bf16 hi/lo splits
    split_bf16<<<(M_*C_/4 + 255)/256, 256>>>(x, xh, xl, M_*C_/4);
    split_bf16<<<(NQKV_*C_/4 + 255)/256, 256>>>(qkv_w, wh, wl, NQKV_*C_/4);
    split_bf16<<<(C_*C_/4 + 255)/256, 256>>>(out_w, oh, ol, C_*C_/4);
    // 2) QKV projection (HMMA tensor cores, bf16 3-split)
    tc_gemm<<<dim3(NQKV_/128, M_/128), 256, TC_SMEM>>>(xh, xl, wh, wl, qkv_ptr, NQKV_);
    // 3) RoPE + reorganize
    rope_reorg<<<(B_*H_*64*(T_/4))/256, 256>>>();
    // 4) Causal flash attention
    attn_kernel<<<dim3(T_/128, H_, B_), 256, attn_smem>>>();
    // 5) Split attention output, then output projection (HMMA)
    split_bf16<<<(M_*C_/4 + 255)/256, 256>>>(attn_ptr, ah, al, M_*C_/4);
    tc_gemm<<<dim3(C_/128, M_/128), 256, TC_SMEM>>>(ah, al, oh, ol, out, C_);
}

// round 9
// speedup vs baseline: 2.3797x; 1.2857x over previous
#include <cuda_runtime.h>
#include <cuda_bf16.h>
#include <math.h>
#include <stdint.h>

#define B_ 2
#define T_ 2048
#define C_ 2048
#define H_ 16
#define D_ 128
#define M_ 4096
#define NQKV_ 6144
#define K_ 2048
#define NCHUNK 32      /* K_/64 */

// ---------------- scratch (device globals: allocation-free) ----------------
__device__ float g_qkv[(size_t)M_*NQKV_];
__device__ float g_attn[(size_t)M_*C_];
__device__ __nv_bfloat16 g_xh[(size_t)M_*C_],    g_xl[(size_t)M_*C_];
__device__ __nv_bfloat16 g_wh[(size_t)NQKV_*C_], g_wl[(size_t)NQKV_*C_];
__device__ __nv_bfloat16 g_oh[(size_t)C_*C_],    g_ol[(size_t)C_*C_];
__device__ __nv_bfloat16 g_ah[(size_t)M_*C_],    g_al[(size_t)M_*C_];
// attention operands (bf16 splits), written by rope_reorg
__device__ __nv_bfloat16 g_qh[(size_t)B_*H_*T_*D_], g_ql[(size_t)B_*H_*T_*D_];
__device__ __nv_bfloat16 g_kh[(size_t)B_*H_*T_*D_], g_kl[(size_t)B_*H_*T_*D_];
__device__ __nv_bfloat16 g_vth[(size_t)B_*H_*D_*T_], g_vtl[(size_t)B_*H_*D_*T_]; // [B,H,D,T]

extern __shared__ __align__(16) char dyn_smem[];

// ---------------- sm_80-class primitives (legal on plain sm_103) -----------
__device__ __forceinline__ uint32_t smem_u32(const void* p) {
    uint32_t a;
    asm("{ .reg .u64 t; cvta.to.shared.u64 t, %1; cvt.u32.u64 %0, t; }"
        : "=r"(a) : "l"(p));
    return a;
}
__device__ __forceinline__ void cp16(uint32_t dst, const void* src) {
    asm volatile("cp.async.cg.shared.global [%0], [%1], 16;"
                 :: "r"(dst), "l"(src) : "memory");
}
__device__ __forceinline__ void cp_commit() {
    asm volatile("cp.async.commit_group;" ::: "memory");
}
__device__ __forceinline__ void cp_wait0() {
    asm volatile("cp.async.wait_group 0;" ::: "memory");
}
__device__ __forceinline__ void ldsm_x4(uint32_t* r, uint32_t addr) {
    asm volatile("ldmatrix.sync.aligned.m8n8.x4.shared.b16 {%0,%1,%2,%3}, [%4];"
                 : "=r"(r[0]), "=r"(r[1]), "=r"(r[2]), "=r"(r[3]) : "r"(addr));
}
__device__ __forceinline__ void mma16816(float* c, const uint32_t* a, const uint32_t* b) {
    asm volatile(
        "mma.sync.aligned.m16n8k16.row.col.f32.bf16.bf16.f32 "
        "{%0,%1,%2,%3}, {%4,%5,%6,%7}, {%8,%9}, {%0,%1,%2,%3};"
        : "+f"(c[0]), "+f"(c[1]), "+f"(c[2]), "+f"(c[3])
        : "r"(a[0]), "r"(a[1]), "r"(a[2]), "r"(a[3]), "r"(b[0]), "r"(b[1]));
}
// SW128 swizzled address inside a [rows][64 bf16] tile (128B rows)
__device__ __forceinline__ uint32_t swz(uint32_t tile_base, int row, int col2 /*bytes*/) {
    return tile_base + ((uint32_t)row << 7) + ((uint32_t)col2 ^ (((uint32_t)row & 7u) << 4));
}
// pack two bf16 into u32 (lo in bits 0-15, hi in bits 16-31)
__device__ __forceinline__ uint32_t pack_bf2(__nv_bfloat16 lo, __nv_bfloat16 hi) {
    return (uint32_t)__bfloat16_as_ushort(lo) | ((uint32_t)__bfloat16_as_ushort(hi) << 16);
}

// ---------------------------------------------------------------------------
// fp32 -> (bf16 hi, bf16 lo) split, 4 elements per thread.
// ---------------------------------------------------------------------------
__global__ void __launch_bounds__(256)
split_bf16(const float* __restrict__ src, __nv_bfloat16* __restrict__ hi,
           __nv_bfloat16* __restrict__ lo, int n4)
{
    const int i = blockIdx.x*256 + threadIdx.x;
    if (i >= n4) return;
    const float4 v = ((const float4*)src)[i];
    float f[4] = {v.x, v.y, v.z, v.w};
    __nv_bfloat16 h[4], l[4];
#pragma unroll
    for (int j = 0; j < 4; ++j) {
        h[j] = __float2bfloat16_rn(f[j]);
        l[j] = __float2bfloat16_rn(f[j] - __bfloat162float(h[j]));
    }
    ((__nv_bfloat162*)hi)[i*2+0] = __halves2bfloat162(h[0], h[1]);
    ((__nv_bfloat162*)hi)[i*2+1] = __halves2bfloat162(h[2], h[3]);
    ((__nv_bfloat162*)lo)[i*2+0] = __halves2bfloat162(l[0], l[1]);
    ((__nv_bfloat162*)lo)[i*2+1] = __halves2bfloat162(l[2], l[3]);
}

// ---------------------------------------------------------------------------
// HMMA bf16 3-split NT GEMM (unchanged from R7, passed).
// ---------------------------------------------------------------------------
#define TCOFF(buf, t) ((uint32_t)(((buf)*4 + (t)) * 16384))
#define TC_SMEM (8*16384)   /* 128 KB */

__device__ __forceinline__ void load_tile_async(uint32_t tile_base,
        const __nv_bfloat16* __restrict__ src, int row0, int k0, int tid)
{
    const char* base = (const char*)(src + (size_t)row0 * K_ + k0);
#pragma unroll
    for (int u = 0; u < 4; ++u) {
        const int c = tid*4 + u;
        const int row = c >> 3, col16 = (c & 7) * 16;
        uint32_t o = (uint32_t)(row*128 + col16);
        o ^= ((o >> 3) & 0x70);
        cp16(tile_base + o, base + (size_t)row * (K_*2) + col16);
    }
}

__global__ void __launch_bounds__(256, 1)
tc_gemm(const __nv_bfloat16* __restrict__ Ah, const __nv_bfloat16* __restrict__ Al,
        const __nv_bfloat16* __restrict__ Bh, const __nv_bfloat16* __restrict__ Bl,
        float* __restrict__ Cout, int N)
{
    const uint32_t sbase = smem_u32(dyn_smem);
    const int tid = threadIdx.x, wid = tid >> 5, lane = tid & 31;
    const int wy = wid >> 2, wx = wid & 3;
    const int m0 = blockIdx.y * 128, n0 = blockIdx.x * 128;
    const int r = lane & 7, g = lane >> 3;

    float acc[4][4][4];
#pragma unroll
    for (int i = 0; i < 4; ++i)
#pragma unroll
        for (int j = 0; j < 4; ++j)
#pragma unroll
            for (int e = 0; e < 4; ++e) acc[i][j][e] = 0.0f;

    load_tile_async(sbase + TCOFF(0,0), Ah, m0, 0, tid);
    load_tile_async(sbase + TCOFF(0,1), Al, m0, 0, tid);
    load_tile_async(sbase + TCOFF(0,2), Bh, n0, 0, tid);
    load_tile_async(sbase + TCOFF(0,3), Bl, n0, 0, tid);
    cp_commit(); cp_wait0();
    __syncthreads();

    for (int chunk = 0; chunk < NCHUNK; ++chunk) {
        const int buf = chunk & 1;
        if (chunk + 1 < NCHUNK) {
            const int k0n = (chunk + 1) * 64;
            load_tile_async(sbase + TCOFF(buf^1,0), Ah, m0, k0n, tid);
            load_tile_async(sbase + TCOFF(buf^1,1), Al, m0, k0n, tid);
            load_tile_async(sbase + TCOFF(buf^1,2), Bh, n0, k0n, tid);
            load_tile_async(sbase + TCOFF(buf^1,3), Bl, n0, k0n, tid);
            cp_commit();
        }
        const uint32_t aH = sbase + TCOFF(buf,0), aL = sbase + TCOFF(buf,1);
        const uint32_t bH = sbase + TCOFF(buf,2), bL = sbase + TCOFF(buf,3);
#pragma unroll
        for (int ks = 0; ks < 4; ++ks) {
            uint32_t ah[4][4], alr[4][4], bh[4][2], blr[4][2];
            const int colA = ks*32 + (g>>1)*16;
            const int colB = ks*32 + (g&1)*16;
#pragma unroll
            for (int i = 0; i < 4; ++i) {
                const int row = wy*64 + i*16 + r + (g&1)*8;
                ldsm_x4(ah[i],  swz(aH, row, colA));
                ldsm_x4(alr[i], swz(aL, row, colA));
            }
#pragma unroll
            for (int jj = 0; jj < 2; ++jj) {
                const int row = wx*32 + jj*16 + r + (g>>1)*8;
                uint32_t t[4];
                ldsm_x4(t, swz(bH, row, colB));
                bh[jj*2][0]=t[0]; bh[jj*2][1]=t[1];
                bh[jj*2+1][0]=t[2]; bh[jj*2+1][1]=t[3];
                ldsm_x4(t, swz(bL, row, colB));
                blr[jj*2][0]=t[0]; blr[jj*2][1]=t[1];
                blr[jj*2+1][0]=t[2]; blr[jj*2+1][1]=t[3];
            }
#pragma unroll
            for (int i = 0; i < 4; ++i)
#pragma unroll
                for (int j = 0; j < 4; ++j) {
                    mma16816(acc[i][j], ah[i],  bh[j]);
                    mma16816(acc[i][j], ah[i],  blr[j]);
                    mma16816(acc[i][j], alr[i], bh[j]);
                }
        }
        if (chunk + 1 < NCHUNK) cp_wait0();
        __syncthreads();
    }
#pragma unroll
    for (int i = 0; i < 4; ++i) {
        const int rm = m0 + wy*64 + i*16 + (lane >> 2);
#pragma unroll
        for (int j = 0; j < 4; ++j) {
            const int cn = n0 + wx*32 + j*8 + (lane & 3)*2;
            *(float2*)&Cout[(size_t)rm*N + cn]     = make_float2(acc[i][j][0], acc[i][j][1]);
            *(float2*)&Cout[(size_t)(rm+8)*N + cn] = make_float2(acc[i][j][2], acc[i][j][3]);
        }
    }
}

// ---------------------------------------------------------------------------
// RoPE + reorganize -> bf16 splits: qh/ql, kh/kl [B,H,T,D]; vth/vtl [B,H,D,T].
// ---------------------------------------------------------------------------
__device__ __forceinline__ void bsplit(float f, __nv_bfloat16& h, __nv_bfloat16& l) {
    h = __float2bfloat16_rn(f);
    l = __float2bfloat16_rn(f - __bfloat162float(h));
}
__global__ void rope_reorg()
{
    const int idx = blockIdx.x * 256 + threadIdx.x;
    const int t4 = idx & 511;
    const int i  = (idx >> 9) & 63;
    const int h  = (idx >> 15) & (H_ - 1);
    const int b  = idx >> 19;
    const int bh = b*H_ + h;
    const int col = h*D_ + i;

    const float mlt = (float)(-9.210340371976184 / 128.0);
    const float div = expf((float)(2*i) * mlt);

#pragma unroll
    for (int u = 0; u < 4; ++u) {
        const int t = t4*4 + u;
        const size_t row = (size_t)(b*T_ + t) * NQKV_;
        const float q1 = g_qkv[row + 0*C_ + col];
        const float q2 = g_qkv[row + 0*C_ + col + 64];
        const float k1 = g_qkv[row + 1*C_ + col];
        const float k2 = g_qkv[row + 1*C_ + col + 64];
        const float v1 = g_qkv[row + 2*C_ + col];
        const float v2 = g_qkv[row + 2*C_ + col + 64];

        float s, c;
        sincosf((float)t * div, &s, &c);
        const float qa = q1*c - q2*s, qb2 = q2*c + q1*s;
        const float ka = k1*c - k2*s, kb2 = k2*c + k1*s;

        const size_t off = ((size_t)bh * T_ + t) * D_ + i;
        __nv_bfloat16 hh, ll;
        bsplit(qa,  hh, ll); g_qh[off]      = hh; g_ql[off]      = ll;
        bsplit(qb2, hh, ll); g_qh[off + 64] = hh; g_ql[off + 64] = ll;
        bsplit(ka,  hh, ll); g_kh[off]      = hh; g_kl[off]      = ll;
        bsplit(kb2, hh, ll); g_kh[off + 64] = hh; g_kl[off + 64] = ll;
        const size_t koff = ((size_t)bh * D_ + i) * T_ + t;
        bsplit(v1, hh, ll); g_vth[koff]          = hh; g_vtl[koff]          = ll;
        bsplit(v2, hh, ll); g_vth[koff + 64*T_]  = hh; g_vtl[koff + 64*T_]  = ll;
    }
}

// ---------------------------------------------------------------------------
// HMMA causal flash attention, bf16 3-split in both phases, fp32 softmax.
// Block = (64-q tile, h, b), 256 threads = 8 warps.
//   S phase : warp grid 4(q)x2(k), warp tile 16q x 32k, K=128 (8 ks)
//   PV phase: warp grid 4(q)x2(d), warp tile 16q x 64d, K=64 (4 ks)
// K/V double-buffered cp.async. Epilogue: reference transposed layout.
// ---------------------------------------------------------------------------
#define AQ_OFF   0u
#define AKV_OFF(buf) (32768u + (buf)*65536u)
#define ASS_OFF  163840u
#define APH_OFF  181248u
#define APL_OFF  189440u
#define AML_OFF  197632u
#define ATT_SMEM (197632 + 768)

__device__ __forceinline__ void att_load64(uint32_t dst, const __nv_bfloat16* src,
                                           size_t pitch, int tid)
{   // [64 rows][64 bf16] subtile, 2 cp16/thread
#pragma unroll
    for (int u = 0; u < 2; ++u) {
        const int c = tid*2 + u;
        const int row = c >> 3, seg = (c & 7) * 16;
        uint32_t o = (uint32_t)(row*128 + seg);
        o ^= ((o >> 3) & 0x70);
        cp16(dst + o, (const char*)(src + (size_t)row*pitch) + seg);
    }
}
__device__ __forceinline__ void att_load128(uint32_t dst, const __nv_bfloat16* src,
                                            size_t pitch, int tid)
{   // [128 rows][64 bf16] tile, 4 cp16/thread
#pragma unroll
    for (int u = 0; u < 4; ++u) {
        const int c = tid*4 + u;
        const int row = c >> 3, seg = (c & 7) * 16;
        uint32_t o = (uint32_t)(row*128 + seg);
        o ^= ((o >> 3) & 0x70);
        cp16(dst + o, (const char*)(src + (size_t)row*pitch) + seg);
    }
}

__global__ void __launch_bounds__(256, 1)
attn_kernel()
{
    const uint32_t sb = smem_u32(dyn_smem);
    float* Ss  = (float*)(dyn_smem + ASS_OFF);
    float* m_s = (float*)(dyn_smem + AML_OFF);
    float* l_s = m_s + 64;
    float* sc_s = l_s + 64;

    const int tid = threadIdx.x, wid = tid >> 5, lane = tid & 31;
    const int r = lane & 7, g = lane >> 3;
    const int wq = wid >> 1, wk = wid & 1;   // also wd = wk in PV
    const int qt = (gridDim.x - 1) - blockIdx.x;
    const int h = blockIdx.y, b = blockIdx.z;
    const size_t hoff  = (size_t)(b*H_ + h) * T_ * D_;
    const size_t hofft = (size_t)(b*H_ + h) * D_ * T_;
    const int q0 = qt * 64;

    // load Q subtiles + first KV tile
    att_load64(sb + AQ_OFF + 0,     g_qh + hoff + (size_t)q0*D_,      D_, tid);
    att_load64(sb + AQ_OFF + 8192,  g_qh + hoff + (size_t)q0*D_ + 64, D_, tid);
    att_load64(sb + AQ_OFF + 16384, g_ql + hoff + (size_t)q0*D_,      D_, tid);
    att_load64(sb + AQ_OFF + 24576, g_ql + hoff + (size_t)q0*D_ + 64, D_, tid);
    {
        const uint32_t kv = sb + AKV_OFF(0);
        att_load64 (kv + 0,     g_kh + hoff, D_, tid);
        att_load64 (kv + 8192,  g_kh + hoff + 64, D_, tid);
        att_load64 (kv + 16384, g_kl + hoff, D_, tid);
        att_load64 (kv + 24576, g_kl + hoff + 64, D_, tid);
        att_load128(kv + 32768, g_vth + hofft, T_, tid);
        att_load128(kv + 49152, g_vtl + hofft, T_, tid);
    }
    cp_commit(); cp_wait0();
    if (tid < 64) { m_s[tid] = -INFINITY; l_s[tid] = 0.0f; }
    __syncthreads();

    float acc[8][4];
#pragma unroll
    for (int j = 0; j < 8; ++j)
#pragma unroll
        for (int e = 0; e < 4; ++e) acc[j][e] = 0.0f;

    const float scl = 0.08838834764831845f;  // 1/sqrt(128)
    const int sr = tid >> 2, sq = tid & 3;    // softmax: 4 lanes/row

    for (int kt = 0; kt <= qt; ++kt) {
        const int buf = kt & 1;
        if (kt < qt) {   // prefetch next KV
            const int k0n = (kt + 1) * 64;
            const uint32_t kv = sb + AKV_OFF(buf^1);
            att_load64 (kv + 0,     g_kh + hoff + (size_t)k0n*D_, D_, tid);
            att_load64 (kv + 8192,  g_kh + hoff + (size_t)k0n*D_ + 64, D_, tid);
            att_load64 (kv + 16384, g_kl + hoff + (size_t)k0n*D_, D_, tid);
            att_load64 (kv + 24576, g_kl + hoff + (size_t)k0n*D_ + 64, D_, tid);
            att_load128(kv + 32768, g_vth + hofft + k0n, T_, tid);
            att_load128(kv + 49152, g_vtl + hofft + k0n, T_, tid);
            cp_commit();
        }
        const uint32_t sQH = sb + AQ_OFF, sQL = sb + AQ_OFF + 16384;
        const uint32_t sKH = sb + AKV_OFF(buf), sKL = sKH + 16384;
        const uint32_t sVH = sb + AKV_OFF(buf) + 32768, sVL = sVH + 16384;

        // ---- S = Q K^T (3-split) ----
        {
            float s[4][4];
#pragma unroll
            for (int j = 0; j < 4; ++j)
#pragma unroll
                for (int e = 0; e < 4; ++e) s[j][e] = 0.0f;
#pragma unroll
            for (int ks = 0; ks < 8; ++ks) {
                const uint32_t subo = (uint32_t)(ks >> 2) * 8192u;
                const int colA = (ks & 3)*32 + (g>>1)*16;
                const int colB = (ks & 3)*32 + (g&1)*16;
                uint32_t ah[4], al[4], bh[4][2], bl[4][2];
                const int rowA = wq*16 + r + (g&1)*8;
                ldsm_x4(ah, swz(sQH + subo, rowA, colA));
                ldsm_x4(al, swz(sQL + subo, rowA, colA));
#pragma unroll
                for (int jj = 0; jj < 2; ++jj) {
                    const int rowB = wk*32 + jj*16 + r + (g>>1)*8;
                    uint32_t t[4];
                    ldsm_x4(t, swz(sKH + subo, rowB, colB));
                    bh[jj*2][0]=t[0]; bh[jj*2][1]=t[1];
                    bh[jj*2+1][0]=t[2]; bh[jj*2+1][1]=t[3];
                    ldsm_x4(t, swz(sKL + subo, rowB, colB));
                    bl[jj*2][0]=t[0]; bl[jj*2][1]=t[1];
                    bl[jj*2+1][0]=t[2]; bl[jj*2+1][1]=t[3];
                }
#pragma unroll
                for (int j = 0; j < 4; ++j) {
                    mma16816(s[j], ah, bh[j]);
                    mma16816(s[j], ah, bl[j]);
                    mma16816(s[j], al, bh[j]);
                }
            }
            // store S (scaled) to fp32 smem
#pragma unroll
            for (int j = 0; j < 4; ++j) {
                const int row0 = wq*16 + (lane >> 2);
                const int cc = wk*32 + j*8 + (lane & 3)*2;
                *(float2*)&Ss[row0*68 + cc]     = make_float2(s[j][0]*scl, s[j][1]*scl);
                *(float2*)&Ss[(row0+8)*68 + cc] = make_float2(s[j][2]*scl, s[j][3]*scl);
            }
        }
        __syncthreads();
        // ---- softmax (fp32) + write P splits ----
        {
            const int k0 = kt * 64;
            float* row = Ss + sr*68;
            int kmax = q0 + sr - k0 + 1;
            if (kmax > 64) kmax = 64;
            const float m_old = m_s[sr];
            float mx = m_old;
#pragma unroll
            for (int c0 = 0; c0 < 16; ++c0) {
                const int c = sq*16 + c0;
                if (c < kmax) mx = fmaxf(mx, row[c]);
            }
            mx = fmaxf(mx, __shfl_xor_sync(0xffffffff, mx, 1));
            mx = fmaxf(mx, __shfl_xor_sync(0xffffffff, mx, 2));
            float sum = 0.0f;
#pragma unroll
            for (int cp = 0; cp < 8; ++cp) {
                const int c = sq*16 + cp*2;
                const float p0 = (c   < kmax) ? __expf(row[c]   - mx) : 0.0f;
                const float p1 = (c+1 < kmax) ? __expf(row[c+1] - mx) : 0.0f;
                sum += p0 + p1;
                const __nv_bfloat16 h0 = __float2bfloat16_rn(p0);
                const __nv_bfloat16 h1 = __float2bfloat16_rn(p1);
                const __nv_bfloat16 l0 = __float2bfloat16_rn(p0 - __bfloat162float(h0));
                const __nv_bfloat16 l1 = __float2bfloat16_rn(p1 - __bfloat162float(h1));
                const int colb = c*2;
                *(uint32_t*)(dyn_smem + (swz(APH_OFF, sr, colb))) = pack_bf2(h0, h1);
                *(uint32_t*)(dyn_smem + (swz(APL_OFF, sr, colb))) = pack_bf2(l0, l1);
            }
            sum += __shfl_xor_sync(0xffffffff, sum, 1);
            sum += __shfl_xor_sync(0xffffffff, sum, 2);
            if (sq == 0) {
                const float sc = __expf(m_old - mx);
                m_s[sr]  = mx;
                l_s[sr]  = l_s[sr] * sc + sum;
                sc_s[sr] = sc;
            }
        }
        __syncthreads();
        // ---- O = O*sc + P V (3-split) ----
        {
            const int row0 = wq*16 + (lane >> 2);
            const float sc0 = sc_s[row0], sc1 = sc_s[row0 + 8];
#pragma unroll
            for (int j = 0; j < 8; ++j) {
                acc[j][0] *= sc0; acc[j][1] *= sc0;
                acc[j][2] *= sc1; acc[j][3] *= sc1;
            }
#pragma unroll
            for (int ks = 0; ks < 4; ++ks) {
                const int colA = ks*32 + (g>>1)*16;
                const int colB = ks*32 + (g&1)*16;
                uint32_t ah[4], al[4], bh[8][2], bl[8][2];
                const int rowA = wq*16 + r + (g&1)*8;
                ldsm_x4(ah, swz(sb + APH_OFF, rowA, colA));
                ldsm_x4(al, swz(sb + APL_OFF, rowA, colA));
#pragma unroll
                for (int jj = 0; jj < 4; ++jj) {
                    const int rowB = wk*64 + jj*16 + r + (g>>1)*8;
                    uint32_t t[4];
                    ldsm_x4(t, swz(sVH, rowB, colB));
                    bh[jj*2][0]=t[0]; bh[jj*2][1]=t[1];
                    bh[jj*2+1][0]=t[2]; bh[jj*2+1][1]=t[3];
                    ldsm_x4(t, swz(sVL, rowB, colB));
                    bl[jj*2][0]=t[0]; bl[jj*2][1]=t[1];
                    bl[jj*2+1][0]=t[2]; bl[jj*2+1][1]=t[3];
                }
#pragma unroll
                for (int j = 0; j < 8; ++j) {
                    mma16816(acc[j], ah, bh[j]);
                    mma16816(acc[j], ah, bl[j]);
                    mma16816(acc[j], al, bh[j]);
                }
            }
        }
        if (kt < qt) cp_wait0();
        __syncthreads();
    }

    // epilogue: normalize + reference layout write
    {
        const int row0 = wq*16 + (lane >> 2);
        const float inv0 = 1.0f / l_s[row0];
        const float inv1 = 1.0f / l_s[row0 + 8];
        const int t0 = q0 + row0, t1 = t0 + 8;
        const int rowA = 128*h + (t0 >> 4), rowB2 = 128*h + (t1 >> 4);
        const int cbase0 = ((t0 & 15) << 7), cbase1 = ((t1 & 15) << 7);
#pragma unroll
        for (int j = 0; j < 8; ++j) {
            const int d = wk*64 + j*8 + (lane & 3)*2;
            *(float2*)&g_attn[(size_t)(b*T_ + rowA)*C_ + cbase0 + d] =
                make_float2(acc[j][0]*inv0, acc[j][1]*inv0);
            *(float2*)&g_attn[(size_t)(b*T_ + rowB2)*C_ + cbase1 + d] =
                make_float2(acc[j][2]*inv1, acc[j][3]*inv1);
        }
    }
}

// ---------------------------------------------------------------------------
extern "C" void kernel_launch(void* const* d_in, const int* in_sizes, int n_in,
                              void* d_out, int out_size)
{
    const float* x = nullptr; const float* qkv_w = nullptr; const float* out_w = nullptr;
    for (int i = 0; i < n_in; ++i) {
        if      (in_sizes[i] == B_*T_*C_) x     = (const float*)d_in[i];
        else if (in_sizes[i] == 3*C_*C_)  qkv_w = (const float*)d_in[i];
        else if (in_sizes[i] == C_*C_)    out_w = (const float*)d_in[i];
    }
    if (!x)     x     = (const float*)d_in[0];
    if (!qkv_w) qkv_w = (const float*)d_in[1];
    if (!out_w) out_w = (const float*)d_in[2];
    float* out = (float*)d_out;

    float *qkv_ptr, *attn_ptr;
    __nv_bfloat16 *xh, *xl, *wh, *wl, *oh, *ol, *ah, *al;
    cudaGetSymbolAddress((void**)&qkv_ptr,  g_qkv);
    cudaGetSymbolAddress((void**)&attn_ptr, g_attn);
    cudaGetSymbolAddress((void**)&xh, g_xh); cudaGetSymbolAddress((void**)&xl, g_xl);
    cudaGetSymbolAddress((void**)&wh, g_wh); cudaGetSymbolAddress((void**)&wl, g_wl);
    cudaGetSymbolAddress((void**)&oh, g_oh); cudaGetSymbolAddress((void**)&ol, g_ol);
    cudaGetSymbolAddress((void**)&ah, g_ah); cudaGetSymbolAddress((void**)&al, g_al);

    cudaFuncSetAttribute(tc_gemm, cudaFuncAttributeMaxDynamicSharedMemorySize, TC_SMEM);
    cudaFuncSetAttribute(attn_kernel, cudaFuncAttributeMaxDynamicSharedMemorySize, ATT_SMEM);

    // 1) fp32 -> bf16 hi/lo splits
    split_bf16<<<(M_*C_/4 + 255)/256, 256>>>(x, xh, xl, M_*C_/4);
    split_bf16<<<(NQKV_*C_/4 + 255)/256, 256>>>(qkv_w, wh, wl, NQKV_*C_/4);
    split_bf16<<<(C_*C_/4 + 255)/256, 256>>>(out_w, oh, ol, C_*C_/4);
    // 2) QKV projection (HMMA)
    tc_gemm<<<dim3(NQKV_/128, M_/128), 256, TC_SMEM>>>(xh, xl, wh, wl, qkv_ptr, NQKV_);
    // 3) RoPE + reorganize -> bf16 split operands
    rope_reorg<<<(B_*H_*64*(T_/4))/256, 256>>>();
    // 4) HMMA causal flash attention
    attn_kernel<<<dim3(T_/64, H_, B_), 256, ATT_SMEM>>>();
    // 5) Split attention output, then output projection (HMMA)
    split_bf16<<<(M_*C_/4 + 255)/256, 256>>>(attn_ptr, ah, al, M_*C_/4);
    tc_gemm<<<dim3(C_/128, M_/128), 256, TC_SMEM>>>(ah, al, oh, ol, out, C_);
}

// round 10
// speedup vs baseline: 2.4294x; 1.0209x over previous
#include <cuda_runtime.h>
#include <cuda_bf16.h>
#include <math.h>
#include <stdint.h>

#define B_ 2
#define T_ 2048
#define C_ 2048
#define H_ 16
#define D_ 128
#define M_ 4096
#define NQKV_ 6144
#define K_ 2048
#define NCHUNK 32      /* K_/64 */

// ---------------- scratch (device globals: allocation-free) ----------------
__device__ float g_qkv[(size_t)M_*NQKV_];
__device__ __nv_bfloat16 g_xh[(size_t)M_*C_],    g_xl[(size_t)M_*C_];
__device__ __nv_bfloat16 g_wh[(size_t)NQKV_*C_], g_wl[(size_t)NQKV_*C_];
__device__ __nv_bfloat16 g_oh[(size_t)C_*C_],    g_ol[(size_t)C_*C_];
__device__ __nv_bfloat16 g_ah[(size_t)M_*C_],    g_al[(size_t)M_*C_];  // attn out (ref layout)
// attention operands (bf16 splits), written by rope_reorg
__device__ __nv_bfloat16 g_qh[(size_t)B_*H_*T_*D_], g_ql[(size_t)B_*H_*T_*D_];
__device__ __nv_bfloat16 g_kh[(size_t)B_*H_*T_*D_], g_kl[(size_t)B_*H_*T_*D_];
__device__ __nv_bfloat16 g_vth[(size_t)B_*H_*D_*T_], g_vtl[(size_t)B_*H_*D_*T_]; // [B,H,D,T]

extern __shared__ __align__(16) char dyn_smem[];

// ---------------- sm_80-class primitives (legal on plain sm_103) -----------
__device__ __forceinline__ uint32_t smem_u32(const void* p) {
    uint32_t a;
    asm("{ .reg .u64 t; cvta.to.shared.u64 t, %1; cvt.u32.u64 %0, t; }"
        : "=r"(a) : "l"(p));
    return a;
}
__device__ __forceinline__ void cp16(uint32_t dst, const void* src) {
    asm volatile("cp.async.cg.shared.global [%0], [%1], 16;"
                 :: "r"(dst), "l"(src) : "memory");
}
__device__ __forceinline__ void cp_commit() {
    asm volatile("cp.async.commit_group;" ::: "memory");
}
__device__ __forceinline__ void cp_wait0() {
    asm volatile("cp.async.wait_group 0;" ::: "memory");
}
__device__ __forceinline__ void cp_wait1() {
    asm volatile("cp.async.wait_group 1;" ::: "memory");
}
__device__ __forceinline__ void ldsm_x4(uint32_t* r, uint32_t addr) {
    asm volatile("ldmatrix.sync.aligned.m8n8.x4.shared.b16 {%0,%1,%2,%3}, [%4];"
                 : "=r"(r[0]), "=r"(r[1]), "=r"(r[2]), "=r"(r[3]) : "r"(addr));
}
__device__ __forceinline__ void mma16816(float* c, const uint32_t* a, const uint32_t* b) {
    asm volatile(
        "mma.sync.aligned.m16n8k16.row.col.f32.bf16.bf16.f32 "
        "{%0,%1,%2,%3}, {%4,%5,%6,%7}, {%8,%9}, {%0,%1,%2,%3};"
        : "+f"(c[0]), "+f"(c[1]), "+f"(c[2]), "+f"(c[3])
        : "r"(a[0]), "r"(a[1]), "r"(a[2]), "r"(a[3]), "r"(b[0]), "r"(b[1]));
}
// SW128 swizzled address inside a [rows][64 bf16] tile (128B rows)
__device__ __forceinline__ uint32_t swz(uint32_t tile_base, int row, int col2 /*bytes*/) {
    return tile_base + ((uint32_t)row << 7) + ((uint32_t)col2 ^ (((uint32_t)row & 7u) << 4));
}
// pack two bf16 into u32 (lo in bits 0-15, hi in bits 16-31)
__device__ __forceinline__ uint32_t pack_bf2(__nv_bfloat16 lo, __nv_bfloat16 hi) {
    return (uint32_t)__bfloat16_as_ushort(lo) | ((uint32_t)__bfloat16_as_ushort(hi) << 16);
}
__device__ __forceinline__ void bsplit(float f, __nv_bfloat16& h, __nv_bfloat16& l) {
    h = __float2bfloat16_rn(f);
    l = __float2bfloat16_rn(f - __bfloat162float(h));
}

// ---------------------------------------------------------------------------
// fp32 -> (bf16 hi, bf16 lo) split, 4 elements per thread.
// ---------------------------------------------------------------------------
__global__ void __launch_bounds__(256)
split_bf16(const float* __restrict__ src, __nv_bfloat16* __restrict__ hi,
           __nv_bfloat16* __restrict__ lo, int n4)
{
    const int i = blockIdx.x*256 + threadIdx.x;
    if (i >= n4) return;
    const float4 v = ((const float4*)src)[i];
    float f[4] = {v.x, v.y, v.z, v.w};
    __nv_bfloat16 h[4], l[4];
#pragma unroll
    for (int j = 0; j < 4; ++j) {
        h[j] = __float2bfloat16_rn(f[j]);
        l[j] = __float2bfloat16_rn(f[j] - __bfloat162float(h[j]));
    }
    ((__nv_bfloat162*)hi)[i*2+0] = __halves2bfloat162(h[0], h[1]);
    ((__nv_bfloat162*)hi)[i*2+1] = __halves2bfloat162(h[2], h[3]);
    ((__nv_bfloat162*)lo)[i*2+0] = __halves2bfloat162(l[0], l[1]);
    ((__nv_bfloat162*)lo)[i*2+1] = __halves2bfloat162(l[2], l[3]);
}

// ---------------------------------------------------------------------------
// HMMA bf16 3-split NT GEMM, 3-stage cp.async pipeline.
// C[m,n] = sum_k A[m,k]*B[n,k], fp32 accum. CTA 128x128, BK=64, 8 warps.
// ---------------------------------------------------------------------------
#define TCOFF(buf, t) ((uint32_t)(((buf)*4 + (t)) * 16384))
#define TC_SMEM (12*16384)   /* 192 KB, 3 stages */

__device__ __forceinline__ void load_tile_async(uint32_t tile_base,
        const __nv_bfloat16* __restrict__ src, int row0, int k0, int tid)
{
    const char* base = (const char*)(src + (size_t)row0 * K_ + k0);
#pragma unroll
    for (int u = 0; u < 4; ++u) {
        const int c = tid*4 + u;
        const int row = c >> 3, col16 = (c & 7) * 16;
        uint32_t o = (uint32_t)(row*128 + col16);
        o ^= ((o >> 3) & 0x70);
        cp16(tile_base + o, base + (size_t)row * (K_*2) + col16);
    }
}

__global__ void __launch_bounds__(256, 1)
tc_gemm(const __nv_bfloat16* __restrict__ Ah, const __nv_bfloat16* __restrict__ Al,
        const __nv_bfloat16* __restrict__ Bh, const __nv_bfloat16* __restrict__ Bl,
        float* __restrict__ Cout, int N)
{
    const uint32_t sbase = smem_u32(dyn_smem);
    const int tid = threadIdx.x, wid = tid >> 5, lane = tid & 31;
    const int wy = wid >> 2, wx = wid & 3;
    const int m0 = blockIdx.y * 128, n0 = blockIdx.x * 128;
    const int r = lane & 7, g = lane >> 3;

    float acc[4][4][4];
#pragma unroll
    for (int i = 0; i < 4; ++i)
#pragma unroll
        for (int j = 0; j < 4; ++j)
#pragma unroll
            for (int e = 0; e < 4; ++e) acc[i][j][e] = 0.0f;

    // prologue: chunks 0,1 -> bufs 0,1
#pragma unroll
    for (int p = 0; p < 2; ++p) {
        load_tile_async(sbase + TCOFF(p,0), Ah, m0, p*64, tid);
        load_tile_async(sbase + TCOFF(p,1), Al, m0, p*64, tid);
        load_tile_async(sbase + TCOFF(p,2), Bh, n0, p*64, tid);
        load_tile_async(sbase + TCOFF(p,3), Bl, n0, p*64, tid);
        cp_commit();
    }

    for (int chunk = 0; chunk < NCHUNK; ++chunk) {
        const int buf = chunk % 3;
        if (chunk == NCHUNK-1) cp_wait0(); else cp_wait1();
        __syncthreads();
        if (chunk + 2 < NCHUNK) {     // issue chunk+2 into buf (chunk+2)%3
            const int nb = (chunk + 2) % 3;
            const int k0n = (chunk + 2) * 64;
            load_tile_async(sbase + TCOFF(nb,0), Ah, m0, k0n, tid);
            load_tile_async(sbase + TCOFF(nb,1), Al, m0, k0n, tid);
            load_tile_async(sbase + TCOFF(nb,2), Bh, n0, k0n, tid);
            load_tile_async(sbase + TCOFF(nb,3), Bl, n0, k0n, tid);
            cp_commit();
        }
        const uint32_t aH = sbase + TCOFF(buf,0), aL = sbase + TCOFF(buf,1);
        const uint32_t bH = sbase + TCOFF(buf,2), bL = sbase + TCOFF(buf,3);
#pragma unroll
        for (int ks = 0; ks < 4; ++ks) {
            uint32_t ah[4][4], alr[4][4], bh[4][2], blr[4][2];
            const int colA = ks*32 + (g>>1)*16;
            const int colB = ks*32 + (g&1)*16;
#pragma unroll
            for (int i = 0; i < 4; ++i) {
                const int row = wy*64 + i*16 + r + (g&1)*8;
                ldsm_x4(ah[i],  swz(aH, row, colA));
                ldsm_x4(alr[i], swz(aL, row, colA));
            }
#pragma unroll
            for (int jj = 0; jj < 2; ++jj) {
                const int row = wx*32 + jj*16 + r + (g>>1)*8;
                uint32_t t[4];
                ldsm_x4(t, swz(bH, row, colB));
                bh[jj*2][0]=t[0]; bh[jj*2][1]=t[1];
                bh[jj*2+1][0]=t[2]; bh[jj*2+1][1]=t[3];
                ldsm_x4(t, swz(bL, row, colB));
                blr[jj*2][0]=t[0]; blr[jj*2][1]=t[1];
                blr[jj*2+1][0]=t[2]; blr[jj*2+1][1]=t[3];
            }
#pragma unroll
            for (int i = 0; i < 4; ++i)
#pragma unroll
                for (int j = 0; j < 4; ++j) {
                    mma16816(acc[i][j], ah[i],  bh[j]);
                    mma16816(acc[i][j], ah[i],  blr[j]);
                    mma16816(acc[i][j], alr[i], bh[j]);
                }
        }
    }
#pragma unroll
    for (int i = 0; i < 4; ++i) {
        const int rm = m0 + wy*64 + i*16 + (lane >> 2);
#pragma unroll
        for (int j = 0; j < 4; ++j) {
            const int cn = n0 + wx*32 + j*8 + (lane & 3)*2;
            *(float2*)&Cout[(size_t)rm*N + cn]     = make_float2(acc[i][j][0], acc[i][j][1]);
            *(float2*)&Cout[(size_t)(rm+8)*N + cn] = make_float2(acc[i][j][2], acc[i][j][3]);
        }
    }
}

// ---------------------------------------------------------------------------
// RoPE + reorganize -> bf16 splits: qh/ql, kh/kl [B,H,T,D]; vth/vtl [B,H,D,T].
// ---------------------------------------------------------------------------
__global__ void rope_reorg()
{
    const int idx = blockIdx.x * 256 + threadIdx.x;
    const int t4 = idx & 511;
    const int i  = (idx >> 9) & 63;
    const int h  = (idx >> 15) & (H_ - 1);
    const int b  = idx >> 19;
    const int bh = b*H_ + h;
    const int col = h*D_ + i;

    const float mlt = (float)(-9.210340371976184 / 128.0);
    const float div = expf((float)(2*i) * mlt);

#pragma unroll
    for (int u = 0; u < 4; ++u) {
        const int t = t4*4 + u;
        const size_t row = (size_t)(b*T_ + t) * NQKV_;
        const float q1 = g_qkv[row + 0*C_ + col];
        const float q2 = g_qkv[row + 0*C_ + col + 64];
        const float k1 = g_qkv[row + 1*C_ + col];
        const float k2 = g_qkv[row + 1*C_ + col + 64];
        const float v1 = g_qkv[row + 2*C_ + col];
        const float v2 = g_qkv[row + 2*C_ + col + 64];

        float s, c;
        sincosf((float)t * div, &s, &c);
        const float qa = q1*c - q2*s, qb2 = q2*c + q1*s;
        const float ka = k1*c - k2*s, kb2 = k2*c + k1*s;

        const size_t off = ((size_t)bh * T_ + t) * D_ + i;
        __nv_bfloat16 hh, ll;
        bsplit(qa,  hh, ll); g_qh[off]      = hh; g_ql[off]      = ll;
        bsplit(qb2, hh, ll); g_qh[off + 64] = hh; g_ql[off + 64] = ll;
        bsplit(ka,  hh, ll); g_kh[off]      = hh; g_kl[off]      = ll;
        bsplit(kb2, hh, ll); g_kh[off + 64] = hh; g_kl[off + 64] = ll;
        const size_t koff = ((size_t)bh * D_ + i) * T_ + t;
        bsplit(v1, hh, ll); g_vth[koff]          = hh; g_vtl[koff]          = ll;
        bsplit(v2, hh, ll); g_vth[koff + 64*T_]  = hh; g_vtl[koff + 64*T_]  = ll;
    }
}

// ---------------------------------------------------------------------------
// HMMA causal flash attention (R9 design), epilogue now writes bf16 hi/lo
// splits directly in the reference layout (fuses the output split kernel).
// ---------------------------------------------------------------------------
#define AQ_OFF   0u
#define AKV_OFF(buf) (32768u + (buf)*65536u)
#define ASS_OFF  163840u
#define APH_OFF  181248u
#define APL_OFF  189440u
#define AML_OFF  197632u
#define ATT_SMEM (197632 + 768)

__device__ __forceinline__ void att_load64(uint32_t dst, const __nv_bfloat16* src,
                                           size_t pitch, int tid)
{
#pragma unroll
    for (int u = 0; u < 2; ++u) {
        const int c = tid*2 + u;
        const int row = c >> 3, seg = (c & 7) * 16;
        uint32_t o = (uint32_t)(row*128 + seg);
        o ^= ((o >> 3) & 0x70);
        cp16(dst + o, (const char*)(src + (size_t)row*pitch) + seg);
    }
}
__device__ __forceinline__ void att_load128(uint32_t dst, const __nv_bfloat16* src,
                                            size_t pitch, int tid)
{
#pragma unroll
    for (int u = 0; u < 4; ++u) {
        const int c = tid*4 + u;
        const int row = c >> 3, seg = (c & 7) * 16;
        uint32_t o = (uint32_t)(row*128 + seg);
        o ^= ((o >> 3) & 0x70);
        cp16(dst + o, (const char*)(src + (size_t)row*pitch) + seg);
    }
}

__global__ void __launch_bounds__(256, 1)
attn_kernel()
{
    const uint32_t sb = smem_u32(dyn_smem);
    float* Ss  = (float*)(dyn_smem + ASS_OFF);
    float* m_s = (float*)(dyn_smem + AML_OFF);
    float* l_s = m_s + 64;
    float* sc_s = l_s + 64;

    const int tid = threadIdx.x, wid = tid >> 5, lane = tid & 31;
    const int r = lane & 7, g = lane >> 3;
    const int wq = wid >> 1, wk = wid & 1;
    const int qt = (gridDim.x - 1) - blockIdx.x;
    const int h = blockIdx.y, b = blockIdx.z;
    const size_t hoff  = (size_t)(b*H_ + h) * T_ * D_;
    const size_t hofft = (size_t)(b*H_ + h) * D_ * T_;
    const int q0 = qt * 64;

    att_load64(sb + AQ_OFF + 0,     g_qh + hoff + (size_t)q0*D_,      D_, tid);
    att_load64(sb + AQ_OFF + 8192,  g_qh + hoff + (size_t)q0*D_ + 64, D_, tid);
    att_load64(sb + AQ_OFF + 16384, g_ql + hoff + (size_t)q0*D_,      D_, tid);
    att_load64(sb + AQ_OFF + 24576, g_ql + hoff + (size_t)q0*D_ + 64, D_, tid);
    {
        const uint32_t kv = sb + AKV_OFF(0);
        att_load64 (kv + 0,     g_kh + hoff, D_, tid);
        att_load64 (kv + 8192,  g_kh + hoff + 64, D_, tid);
        att_load64 (kv + 16384, g_kl + hoff, D_, tid);
        att_load64 (kv + 24576, g_kl + hoff + 64, D_, tid);
        att_load128(kv + 32768, g_vth + hofft, T_, tid);
        att_load128(kv + 49152, g_vtl + hofft, T_, tid);
    }
    cp_commit(); cp_wait0();
    if (tid < 64) { m_s[tid] = -INFINITY; l_s[tid] = 0.0f; }
    __syncthreads();

    float acc[8][4];
#pragma unroll
    for (int j = 0; j < 8; ++j)
#pragma unroll
        for (int e = 0; e < 4; ++e) acc[j][e] = 0.0f;

    const float scl = 0.08838834764831845f;
    const int sr = tid >> 2, sq = tid & 3;

    for (int kt = 0; kt <= qt; ++kt) {
        const int buf = kt & 1;
        if (kt < qt) {
            const int k0n = (kt + 1) * 64;
            const uint32_t kv = sb + AKV_OFF(buf^1);
            att_load64 (kv + 0,     g_kh + hoff + (size_t)k0n*D_, D_, tid);
            att_load64 (kv + 8192,  g_kh + hoff + (size_t)k0n*D_ + 64, D_, tid);
            att_load64 (kv + 16384, g_kl + hoff + (size_t)k0n*D_, D_, tid);
            att_load64 (kv + 24576, g_kl + hoff + (size_t)k0n*D_ + 64, D_, tid);
            att_load128(kv + 32768, g_vth + hofft + k0n, T_, tid);
            att_load128(kv + 49152, g_vtl + hofft + k0n, T_, tid);
            cp_commit();
        }
        const uint32_t sQH = sb + AQ_OFF, sQL = sb + AQ_OFF + 16384;
        const uint32_t sKH = sb + AKV_OFF(buf), sKL = sKH + 16384;
        const uint32_t sVH = sb + AKV_OFF(buf) + 32768, sVL = sVH + 16384;

        // ---- S = Q K^T (3-split) ----
        {
            float s[4][4];
#pragma unroll
            for (int j = 0; j < 4; ++j)
#pragma unroll
                for (int e = 0; e < 4; ++e) s[j][e] = 0.0f;
#pragma unroll
            for (int ks = 0; ks < 8; ++ks) {
                const uint32_t subo = (uint32_t)(ks >> 2) * 8192u;
                const int colA = (ks & 3)*32 + (g>>1)*16;
                const int colB = (ks & 3)*32 + (g&1)*16;
                uint32_t ah[4], al[4], bh[4][2], bl[4][2];
                const int rowA = wq*16 + r + (g&1)*8;
                ldsm_x4(ah, swz(sQH + subo, rowA, colA));
                ldsm_x4(al, swz(sQL + subo, rowA, colA));
#pragma unroll
                for (int jj = 0; jj < 2; ++jj) {
                    const int rowB = wk*32 + jj*16 + r + (g>>1)*8;
                    uint32_t t[4];
                    ldsm_x4(t, swz(sKH + subo, rowB, colB));
                    bh[jj*2][0]=t[0]; bh[jj*2][1]=t[1];
                    bh[jj*2+1][0]=t[2]; bh[jj*2+1][1]=t[3];
                    ldsm_x4(t, swz(sKL + subo, rowB, colB));
                    bl[jj*2][0]=t[0]; bl[jj*2][1]=t[1];
                    bl[jj*2+1][0]=t[2]; bl[jj*2+1][1]=t[3];
                }
#pragma unroll
                for (int j = 0; j < 4; ++j) {
                    mma16816(s[j], ah, bh[j]);
                    mma16816(s[j], ah, bl[j]);
                    mma16816(s[j], al, bh[j]);
                }
            }
#pragma unroll
            for (int j = 0; j < 4; ++j) {
                const int row0 = wq*16 + (lane >> 2);
                const int cc = wk*32 + j*8 + (lane & 3)*2;
                *(float2*)&Ss[row0*68 + cc]     = make_float2(s[j][0]*scl, s[j][1]*scl);
                *(float2*)&Ss[(row0+8)*68 + cc] = make_float2(s[j][2]*scl, s[j][3]*scl);
            }
        }
        __syncthreads();
        // ---- softmax (fp32) + write P splits ----
        {
            const int k0 = kt * 64;
            float* row = Ss + sr*68;
            int kmax = q0 + sr - k0 + 1;
            if (kmax > 64) kmax = 64;
            const float m_old = m_s[sr];
            float mx = m_old;
#pragma unroll
            for (int c0 = 0; c0 < 16; ++c0) {
                const int c = sq*16 + c0;
                if (c < kmax) mx = fmaxf(mx, row[c]);
            }
            mx = fmaxf(mx, __shfl_xor_sync(0xffffffff, mx, 1));
            mx = fmaxf(mx, __shfl_xor_sync(0xffffffff, mx, 2));
            float sum = 0.0f;
#pragma unroll
            for (int cp = 0; cp < 8; ++cp) {
                const int c = sq*16 + cp*2;
                const float p0 = (c   < kmax) ? __expf(row[c]   - mx) : 0.0f;
                const float p1 = (c+1 < kmax) ? __expf(row[c+1] - mx) : 0.0f;
                sum += p0 + p1;
                __nv_bfloat16 h0, l0, h1, l1;
                bsplit(p0, h0, l0); bsplit(p1, h1, l1);
                const int colb = c*2;
                *(uint32_t*)(dyn_smem + swz(APH_OFF, sr, colb)) = pack_bf2(h0, h1);
                *(uint32_t*)(dyn_smem + swz(APL_OFF, sr, colb)) = pack_bf2(l0, l1);
            }
            sum += __shfl_xor_sync(0xffffffff, sum, 1);
            sum += __shfl_xor_sync(0xffffffff, sum, 2);
            if (sq == 0) {
                const float sc = __expf(m_old - mx);
                m_s[sr]  = mx;
                l_s[sr]  = l_s[sr] * sc + sum;
                sc_s[sr] = sc;
            }
        }
        __syncthreads();
        // ---- O = O*sc + P V (3-split) ----
        {
            const int row0 = wq*16 + (lane >> 2);
            const float sc0 = sc_s[row0], sc1 = sc_s[row0 + 8];
#pragma unroll
            for (int j = 0; j < 8; ++j) {
                acc[j][0] *= sc0; acc[j][1] *= sc0;
                acc[j][2] *= sc1; acc[j][3] *= sc1;
            }
#pragma unroll
            for (int ks = 0; ks < 4; ++ks) {
                const int colA = ks*32 + (g>>1)*16;
                const int colB = ks*32 + (g&1)*16;
                uint32_t ah[4], al[4], bh[8][2], bl[8][2];
                const int rowA = wq*16 + r + (g&1)*8;
                ldsm_x4(ah, swz(sb + APH_OFF, rowA, colA));
                ldsm_x4(al, swz(sb + APL_OFF, rowA, colA));
#pragma unroll
                for (int jj = 0; jj < 4; ++jj) {
                    const int rowB = wk*64 + jj*16 + r + (g>>1)*8;
                    uint32_t t[4];
                    ldsm_x4(t, swz(sVH, rowB, colB));
                    bh[jj*2][0]=t[0]; bh[jj*2][1]=t[1];
                    bh[jj*2+1][0]=t[2]; bh[jj*2+1][1]=t[3];
                    ldsm_x4(t, swz(sVL, rowB, colB));
                    bl[jj*2][0]=t[0]; bl[jj*2][1]=t[1];
                    bl[jj*2+1][0]=t[2]; bl[jj*2+1][1]=t[3];
                }
#pragma unroll
                for (int j = 0; j < 8; ++j) {
                    mma16816(acc[j], ah, bh[j]);
                    mma16816(acc[j], ah, bl[j]);
                    mma16816(acc[j], al, bh[j]);
                }
            }
        }
        if (kt < qt) cp_wait0();
        __syncthreads();
    }

    // epilogue: normalize + split to bf16 hi/lo, reference layout
    {
        const int row0 = wq*16 + (lane >> 2);
        const float inv0 = 1.0f / l_s[row0];
        const float inv1 = 1.0f / l_s[row0 + 8];
        const int t0 = q0 + row0, t1 = t0 + 8;
        const int rowA = 128*h + (t0 >> 4), rowB2 = 128*h + (t1 >> 4);
        const int cbase0 = ((t0 & 15) << 7), cbase1 = ((t1 & 15) << 7);
#pragma unroll
        for (int j = 0; j < 8; ++j) {
            const int d = wk*64 + j*8 + (lane & 3)*2;
            const size_t i0 = (size_t)(b*T_ + rowA)*C_ + cbase0 + d;
            const size_t i1 = (size_t)(b*T_ + rowB2)*C_ + cbase1 + d;
            __nv_bfloat16 h0, l0, h1, l1;
            bsplit(acc[j][0]*inv0, h0, l0); bsplit(acc[j][1]*inv0, h1, l1);
            *(uint32_t*)&g_ah[i0] = pack_bf2(h0, h1);
            *(uint32_t*)&g_al[i0] = pack_bf2(l0, l1);
            bsplit(acc[j][2]*inv1, h0, l0); bsplit(acc[j][3]*inv1, h1, l1);
            *(uint32_t*)&g_ah[i1] = pack_bf2(h0, h1);
            *(uint32_t*)&g_al[i1] = pack_bf2(l0, l1);
        }
    }
}

// ---------------------------------------------------------------------------
extern "C" void kernel_launch(void* const* d_in, const int* in_sizes, int n_in,
                              void* d_out, int out_size)
{
    const float* x = nullptr; const float* qkv_w = nullptr; const float* out_w = nullptr;
    for (int i = 0; i < n_in; ++i) {
        if      (in_sizes[i] == B_*T_*C_) x     = (const float*)d_in[i];
        else if (in_sizes[i] == 3*C_*C_)  qkv_w = (const float*)d_in[i];
        else if (in_sizes[i] == C_*C_)    out_w = (const float*)d_in[i];
    }
    if (!x)     x     = (const float*)d_in[0];
    if (!qkv_w) qkv_w = (const float*)d_in[1];
    if (!out_w) out_w = (const float*)d_in[2];
    float* out = (float*)d_out;

    float *qkv_ptr;
    __nv_bfloat16 *xh, *xl, *wh, *wl, *oh, *ol, *ah, *al;
    cudaGetSymbolAddress((void**)&qkv_ptr,  g_qkv);
    cudaGetSymbolAddress((void**)&xh, g_xh); cudaGetSymbolAddress((void**)&xl, g_xl);
    cudaGetSymbolAddress((void**)&wh, g_wh); cudaGetSymbolAddress((void**)&wl, g_wl);
    cudaGetSymbolAddress((void**)&oh, g_oh); cudaGetSymbolAddress((void**)&ol, g_ol);
    cudaGetSymbolAddress((void**)&ah, g_ah); cudaGetSymbolAddress((void**)&al, g_al);

    cudaFuncSetAttribute(tc_gemm, cudaFuncAttributeMaxDynamicSharedMemorySize, TC_SMEM);
    cudaFuncSetAttribute(attn_kernel, cudaFuncAttributeMaxDynamicSharedMemorySize, ATT_SMEM);

    // 1) fp32 -> bf16 hi/lo splits
    split_bf16<<<(M_*C_/4 + 255)/256, 256>>>(x, xh, xl, M_*C_/4);
    split_bf16<<<(NQKV_*C_/4 + 255)/256, 256>>>(qkv_w, wh, wl, NQKV_*C_/4);
    split_bf16<<<(C_*C_/4 + 255)/256, 256>>>(out_w, oh, ol, C_*C_/4);
    // 2) QKV projection (HMMA, 3-stage pipeline)
    tc_gemm<<<dim3(NQKV_/128, M_/128), 256, TC_SMEM>>>(xh, xl, wh, wl, qkv_ptr, NQKV_);
    // 3) RoPE + reorganize -> bf16 split operands
    rope_reorg<<<(B_*H_*64*(T_/4))/256, 256>>>();
    // 4) HMMA causal flash attention (writes g_ah/g_al directly)
    attn_kernel<<<dim3(T_/64, H_, B_), 256, ATT_SMEM>>>();
    // 5) Output projection (HMMA)
    tc_gemm<<<dim3(C_/128, M_/128), 256, TC_SMEM>>>(ah, al, oh, ol, out, C_);
}

// round 11
// speedup vs baseline: 2.4306x; 1.0005x over previous
#include <cuda_runtime.h>
#include <cuda_bf16.h>
#include <math.h>
#include <stdint.h>

#define B_ 2
#define T_ 2048
#define C_ 2048
#define H_ 16
#define D_ 128
#define M_ 4096
#define NQKV_ 6144
#define K_ 2048
#define NCHUNK 32      /* K_/64 */

// ---------------- scratch (device globals: allocation-free) ----------------
__device__ float g_qkv[(size_t)M_*NQKV_];
__device__ __nv_bfloat16 g_xh[(size_t)M_*C_],    g_xl[(size_t)M_*C_];
__device__ __nv_bfloat16 g_wh[(size_t)NQKV_*C_], g_wl[(size_t)NQKV_*C_];
__device__ __nv_bfloat16 g_oh[(size_t)C_*C_],    g_ol[(size_t)C_*C_];
__device__ __nv_bfloat16 g_ah[(size_t)M_*C_],    g_al[(size_t)M_*C_];  // attn out (ref layout)
// attention operands (bf16 splits), written by rope_reorg
__device__ __nv_bfloat16 g_qh[(size_t)B_*H_*T_*D_], g_ql[(size_t)B_*H_*T_*D_];
__device__ __nv_bfloat16 g_kh[(size_t)B_*H_*T_*D_], g_kl[(size_t)B_*H_*T_*D_];
__device__ __nv_bfloat16 g_vth[(size_t)B_*H_*D_*T_], g_vtl[(size_t)B_*H_*D_*T_]; // [B,H,D,T]

extern __shared__ __align__(16) char dyn_smem[];

// ---------------- sm_80-class primitives (legal on plain sm_103) -----------
__device__ __forceinline__ uint32_t smem_u32(const void* p) {
    uint32_t a;
    asm("{ .reg .u64 t; cvta.to.shared.u64 t, %1; cvt.u32.u64 %0, t; }"
        : "=r"(a) : "l"(p));
    return a;
}
__device__ __forceinline__ void cp16(uint32_t dst, const void* src) {
    asm volatile("cp.async.cg.shared.global [%0], [%1], 16;"
                 :: "r"(dst), "l"(src) : "memory");
}
__device__ __forceinline__ void cp_commit() {
    asm volatile("cp.async.commit_group;" ::: "memory");
}
__device__ __forceinline__ void cp_wait0() {
    asm volatile("cp.async.wait_group 0;" ::: "memory");
}
__device__ __forceinline__ void cp_wait1() {
    asm volatile("cp.async.wait_group 1;" ::: "memory");
}
__device__ __forceinline__ void ldsm_x4(uint32_t* r, uint32_t addr) {
    asm volatile("ldmatrix.sync.aligned.m8n8.x4.shared.b16 {%0,%1,%2,%3}, [%4];"
                 : "=r"(r[0]), "=r"(r[1]), "=r"(r[2]), "=r"(r[3]) : "r"(addr));
}
__device__ __forceinline__ void mma16816(float* c, const uint32_t* a, const uint32_t* b) {
    asm volatile(
        "mma.sync.aligned.m16n8k16.row.col.f32.bf16.bf16.f32 "
        "{%0,%1,%2,%3}, {%4,%5,%6,%7}, {%8,%9}, {%0,%1,%2,%3};"
        : "+f"(c[0]), "+f"(c[1]), "+f"(c[2]), "+f"(c[3])
        : "r"(a[0]), "r"(a[1]), "r"(a[2]), "r"(a[3]), "r"(b[0]), "r"(b[1]));
}
// SW128 swizzled address inside a [rows][64 bf16] tile (128B rows)
__device__ __forceinline__ uint32_t swz(uint32_t tile_base, int row, int col2 /*bytes*/) {
    return tile_base + ((uint32_t)row << 7) + ((uint32_t)col2 ^ (((uint32_t)row & 7u) << 4));
}
// pack two bf16 into u32 (lo in bits 0-15, hi in bits 16-31)
__device__ __forceinline__ uint32_t pack_bf2(__nv_bfloat16 lo, __nv_bfloat16 hi) {
    return (uint32_t)__bfloat16_as_ushort(lo) | ((uint32_t)__bfloat16_as_ushort(hi) << 16);
}
__device__ __forceinline__ void bsplit(float f, __nv_bfloat16& h, __nv_bfloat16& l) {
    h = __float2bfloat16_rn(f);
    l = __float2bfloat16_rn(f - __bfloat162float(h));
}

// ---------------------------------------------------------------------------
// fp32 -> (bf16 hi, bf16 lo) split, 4 elements per thread.
// ---------------------------------------------------------------------------
__global__ void __launch_bounds__(256)
split_bf16(const float* __restrict__ src, __nv_bfloat16* __restrict__ hi,
           __nv_bfloat16* __restrict__ lo, int n4)
{
    const int i = blockIdx.x*256 + threadIdx.x;
    if (i >= n4) return;
    const float4 v = ((const float4*)src)[i];
    float f[4] = {v.x, v.y, v.z, v.w};
    __nv_bfloat16 h[4], l[4];
#pragma unroll
    for (int j = 0; j < 4; ++j) {
        h[j] = __float2bfloat16_rn(f[j]);
        l[j] = __float2bfloat16_rn(f[j] - __bfloat162float(h[j]));
    }
    ((__nv_bfloat162*)hi)[i*2+0] = __halves2bfloat162(h[0], h[1]);
    ((__nv_bfloat162*)hi)[i*2+1] = __halves2bfloat162(h[2], h[3]);
    ((__nv_bfloat162*)lo)[i*2+0] = __halves2bfloat162(l[0], l[1]);
    ((__nv_bfloat162*)lo)[i*2+1] = __halves2bfloat162(l[2], l[3]);
}

// ---------------------------------------------------------------------------
// HMMA bf16 3-split NT GEMM, 3-stage cp.async pipeline + register-pipelined
// fragments (ldsm for ks+1 issued before mma of ks).
// ---------------------------------------------------------------------------
#define TCOFF(buf, t) ((uint32_t)(((buf)*4 + (t)) * 16384))
#define TC_SMEM (12*16384)   /* 192 KB, 3 stages */

__device__ __forceinline__ void load_tile_async(uint32_t tile_base,
        const __nv_bfloat16* __restrict__ src, int row0, int k0, int tid)
{
    const char* base = (const char*)(src + (size_t)row0 * K_ + k0);
#pragma unroll
    for (int u = 0; u < 4; ++u) {
        const int c = tid*4 + u;
        const int row = c >> 3, col16 = (c & 7) * 16;
        uint32_t o = (uint32_t)(row*128 + col16);
        o ^= ((o >> 3) & 0x70);
        cp16(tile_base + o, base + (size_t)row * (K_*2) + col16);
    }
}

__global__ void __launch_bounds__(256, 1)
tc_gemm(const __nv_bfloat16* __restrict__ Ah, const __nv_bfloat16* __restrict__ Al,
        const __nv_bfloat16* __restrict__ Bh, const __nv_bfloat16* __restrict__ Bl,
        float* __restrict__ Cout, int N)
{
    const uint32_t sbase = smem_u32(dyn_smem);
    const int tid = threadIdx.x, wid = tid >> 5, lane = tid & 31;
    const int wy = wid >> 2, wx = wid & 3;
    const int m0 = blockIdx.y * 128, n0 = blockIdx.x * 128;
    const int r = lane & 7, g = lane >> 3;

    float acc[4][4][4];
#pragma unroll
    for (int i = 0; i < 4; ++i)
#pragma unroll
        for (int j = 0; j < 4; ++j)
#pragma unroll
            for (int e = 0; e < 4; ++e) acc[i][j][e] = 0.0f;

    // prologue: chunks 0,1 -> bufs 0,1
#pragma unroll
    for (int p = 0; p < 2; ++p) {
        load_tile_async(sbase + TCOFF(p,0), Ah, m0, p*64, tid);
        load_tile_async(sbase + TCOFF(p,1), Al, m0, p*64, tid);
        load_tile_async(sbase + TCOFF(p,2), Bh, n0, p*64, tid);
        load_tile_async(sbase + TCOFF(p,3), Bl, n0, p*64, tid);
        cp_commit();
    }

    uint32_t ah[2][4][4], alr[2][4][4], bh[2][4][2], blr[2][4][2];

    for (int chunk = 0; chunk < NCHUNK; ++chunk) {
        const int buf = chunk % 3;
        if (chunk == NCHUNK-1) cp_wait0(); else cp_wait1();
        __syncthreads();
        if (chunk + 2 < NCHUNK) {
            const int nb = (chunk + 2) % 3;
            const int k0n = (chunk + 2) * 64;
            load_tile_async(sbase + TCOFF(nb,0), Ah, m0, k0n, tid);
            load_tile_async(sbase + TCOFF(nb,1), Al, m0, k0n, tid);
            load_tile_async(sbase + TCOFF(nb,2), Bh, n0, k0n, tid);
            load_tile_async(sbase + TCOFF(nb,3), Bl, n0, k0n, tid);
            cp_commit();
        }
        const uint32_t aH = sbase + TCOFF(buf,0), aL = sbase + TCOFF(buf,1);
        const uint32_t bH = sbase + TCOFF(buf,2), bL = sbase + TCOFF(buf,3);

        // fragment loader for one ks step into ping-pong slot pb
        auto load_frags = [&](int ks, int pb) {
            const int colA = ks*32 + (g>>1)*16;
            const int colB = ks*32 + (g&1)*16;
#pragma unroll
            for (int i = 0; i < 4; ++i) {
                const int row = wy*64 + i*16 + r + (g&1)*8;
                ldsm_x4(ah[pb][i],  swz(aH, row, colA));
                ldsm_x4(alr[pb][i], swz(aL, row, colA));
            }
#pragma unroll
            for (int jj = 0; jj < 2; ++jj) {
                const int row = wx*32 + jj*16 + r + (g>>1)*8;
                uint32_t t[4];
                ldsm_x4(t, swz(bH, row, colB));
                bh[pb][jj*2][0]=t[0]; bh[pb][jj*2][1]=t[1];
                bh[pb][jj*2+1][0]=t[2]; bh[pb][jj*2+1][1]=t[3];
                ldsm_x4(t, swz(bL, row, colB));
                blr[pb][jj*2][0]=t[0]; blr[pb][jj*2][1]=t[1];
                blr[pb][jj*2+1][0]=t[2]; blr[pb][jj*2+1][1]=t[3];
            }
        };

        load_frags(0, 0);
#pragma unroll
        for (int ks = 0; ks < 4; ++ks) {
            const int cur = ks & 1;
            if (ks < 3) load_frags(ks + 1, cur ^ 1);   // hide LDSM under MMA
#pragma unroll
            for (int i = 0; i < 4; ++i)
#pragma unroll
                for (int j = 0; j < 4; ++j) {
                    mma16816(acc[i][j], ah[cur][i],  bh[cur][j]);
                    mma16816(acc[i][j], ah[cur][i],  blr[cur][j]);
                    mma16816(acc[i][j], alr[cur][i], bh[cur][j]);
                }
        }
    }
#pragma unroll
    for (int i = 0; i < 4; ++i) {
        const int rm = m0 + wy*64 + i*16 + (lane >> 2);
#pragma unroll
        for (int j = 0; j < 4; ++j) {
            const int cn = n0 + wx*32 + j*8 + (lane & 3)*2;
            *(float2*)&Cout[(size_t)rm*N + cn]     = make_float2(acc[i][j][0], acc[i][j][1]);
            *(float2*)&Cout[(size_t)(rm+8)*N + cn] = make_float2(acc[i][j][2], acc[i][j][3]);
        }
    }
}

// ---------------------------------------------------------------------------
// RoPE + reorganize -> bf16 splits: qh/ql, kh/kl [B,H,T,D]; vth/vtl [B,H,D,T].
// ---------------------------------------------------------------------------
__global__ void rope_reorg()
{
    const int idx = blockIdx.x * 256 + threadIdx.x;
    const int t4 = idx & 511;
    const int i  = (idx >> 9) & 63;
    const int h  = (idx >> 15) & (H_ - 1);
    const int b  = idx >> 19;
    const int bh = b*H_ + h;
    const int col = h*D_ + i;

    const float mlt = (float)(-9.210340371976184 / 128.0);
    const float div = expf((float)(2*i) * mlt);

#pragma unroll
    for (int u = 0; u < 4; ++u) {
        const int t = t4*4 + u;
        const size_t row = (size_t)(b*T_ + t) * NQKV_;
        const float q1 = g_qkv[row + 0*C_ + col];
        const float q2 = g_qkv[row + 0*C_ + col + 64];
        const float k1 = g_qkv[row + 1*C_ + col];
        const float k2 = g_qkv[row + 1*C_ + col + 64];
        const float v1 = g_qkv[row + 2*C_ + col];
        const float v2 = g_qkv[row + 2*C_ + col + 64];

        float s, c;
        sincosf((float)t * div, &s, &c);
        const float qa = q1*c - q2*s, qb2 = q2*c + q1*s;
        const float ka = k1*c - k2*s, kb2 = k2*c + k1*s;

        const size_t off = ((size_t)bh * T_ + t) * D_ + i;
        __nv_bfloat16 hh, ll;
        bsplit(qa,  hh, ll); g_qh[off]      = hh; g_ql[off]      = ll;
        bsplit(qb2, hh, ll); g_qh[off + 64] = hh; g_ql[off + 64] = ll;
        bsplit(ka,  hh, ll); g_kh[off]      = hh; g_kl[off]      = ll;
        bsplit(kb2, hh, ll); g_kh[off + 64] = hh; g_kl[off + 64] = ll;
        const size_t koff = ((size_t)bh * D_ + i) * T_ + t;
        bsplit(v1, hh, ll); g_vth[koff]          = hh; g_vtl[koff]          = ll;
        bsplit(v2, hh, ll); g_vth[koff + 64*T_]  = hh; g_vtl[koff + 64*T_]  = ll;
    }
}

// ---------------------------------------------------------------------------
// HMMA causal flash attention; S and PV phases register-pipelined.
// ---------------------------------------------------------------------------
#define AQ_OFF   0u
#define AKV_OFF(buf) (32768u + (buf)*65536u)
#define ASS_OFF  163840u
#define APH_OFF  181248u
#define APL_OFF  189440u
#define AML_OFF  197632u
#define ATT_SMEM (197632 + 768)

__device__ __forceinline__ void att_load64(uint32_t dst, const __nv_bfloat16* src,
                                           size_t pitch, int tid)
{
#pragma unroll
    for (int u = 0; u < 2; ++u) {
        const int c = tid*2 + u;
        const int row = c >> 3, seg = (c & 7) * 16;
        uint32_t o = (uint32_t)(row*128 + seg);
        o ^= ((o >> 3) & 0x70);
        cp16(dst + o, (const char*)(src + (size_t)row*pitch) + seg);
    }
}
__device__ __forceinline__ void att_load128(uint32_t dst, const __nv_bfloat16* src,
                                            size_t pitch, int tid)
{
#pragma unroll
    for (int u = 0; u < 4; ++u) {
        const int c = tid*4 + u;
        const int row = c >> 3, seg = (c & 7) * 16;
        uint32_t o = (uint32_t)(row*128 + seg);
        o ^= ((o >> 3) & 0x70);
        cp16(dst + o, (const char*)(src + (size_t)row*pitch) + seg);
    }
}

__global__ void __launch_bounds__(256, 1)
attn_kernel()
{
    const uint32_t sb = smem_u32(dyn_smem);
    float* Ss  = (float*)(dyn_smem + ASS_OFF);
    float* m_s = (float*)(dyn_smem + AML_OFF);
    float* l_s = m_s + 64;
    float* sc_s = l_s + 64;

    const int tid = threadIdx.x, wid = tid >> 5, lane = tid & 31;
    const int r = lane & 7, g = lane >> 3;
    const int wq = wid >> 1, wk = wid & 1;
    const int qt = (gridDim.x - 1) - blockIdx.x;
    const int h = blockIdx.y, b = blockIdx.z;
    const size_t hoff  = (size_t)(b*H_ + h) * T_ * D_;
    const size_t hofft = (size_t)(b*H_ + h) * D_ * T_;
    const int q0 = qt * 64;

    att_load64(sb + AQ_OFF + 0,     g_qh + hoff + (size_t)q0*D_,      D_, tid);
    att_load64(sb + AQ_OFF + 8192,  g_qh + hoff + (size_t)q0*D_ + 64, D_, tid);
    att_load64(sb + AQ_OFF + 16384, g_ql + hoff + (size_t)q0*D_,      D_, tid);
    att_load64(sb + AQ_OFF + 24576, g_ql + hoff + (size_t)q0*D_ + 64, D_, tid);
    {
        const uint32_t kv = sb + AKV_OFF(0);
        att_load64 (kv + 0,     g_kh + hoff, D_, tid);
        att_load64 (kv + 8192,  g_kh + hoff + 64, D_, tid);
        att_load64 (kv + 16384, g_kl + hoff, D_, tid);
        att_load64 (kv + 24576, g_kl + hoff + 64, D_, tid);
        att_load128(kv + 32768, g_vth + hofft, T_, tid);
        att_load128(kv + 49152, g_vtl + hofft, T_, tid);
    }
    cp_commit(); cp_wait0();
    if (tid < 64) { m_s[tid] = -INFINITY; l_s[tid] = 0.0f; }
    __syncthreads();

    float acc[8][4];
#pragma unroll
    for (int j = 0; j < 8; ++j)
#pragma unroll
        for (int e = 0; e < 4; ++e) acc[j][e] = 0.0f;

    const float scl = 0.08838834764831845f;
    const int sr = tid >> 2, sq = tid & 3;

    for (int kt = 0; kt <= qt; ++kt) {
        const int buf = kt & 1;
        if (kt < qt) {
            const int k0n = (kt + 1) * 64;
            const uint32_t kv = sb + AKV_OFF(buf^1);
            att_load64 (kv + 0,     g_kh + hoff + (size_t)k0n*D_, D_, tid);
            att_load64 (kv + 8192,  g_kh + hoff + (size_t)k0n*D_ + 64, D_, tid);
            att_load64 (kv + 16384, g_kl + hoff + (size_t)k0n*D_, D_, tid);
            att_load64 (kv + 24576, g_kl + hoff + (size_t)k0n*D_ + 64, D_, tid);
            att_load128(kv + 32768, g_vth + hofft + k0n, T_, tid);
            att_load128(kv + 49152, g_vtl + hofft + k0n, T_, tid);
            cp_commit();
        }
        const uint32_t sQH = sb + AQ_OFF, sQL = sb + AQ_OFF + 16384;
        const uint32_t sKH = sb + AKV_OFF(buf), sKL = sKH + 16384;
        const uint32_t sVH = sb + AKV_OFF(buf) + 32768, sVL = sVH + 16384;

        // ---- S = Q K^T (3-split, register-pipelined) ----
        {
            float s[4][4];
#pragma unroll
            for (int j = 0; j < 4; ++j)
#pragma unroll
                for (int e = 0; e < 4; ++e) s[j][e] = 0.0f;

            uint32_t ah[2][4], al[2][4], bh[2][4][2], bl[2][4][2];
            auto loadS = [&](int ks, int pb) {
                const uint32_t subo = (uint32_t)(ks >> 2) * 8192u;
                const int colA = (ks & 3)*32 + (g>>1)*16;
                const int colB = (ks & 3)*32 + (g&1)*16;
                const int rowA = wq*16 + r + (g&1)*8;
                ldsm_x4(ah[pb], swz(sQH + subo, rowA, colA));
                ldsm_x4(al[pb], swz(sQL + subo, rowA, colA));
#pragma unroll
                for (int jj = 0; jj < 2; ++jj) {
                    const int rowB = wk*32 + jj*16 + r + (g>>1)*8;
                    uint32_t t[4];
                    ldsm_x4(t, swz(sKH + subo, rowB, colB));
                    bh[pb][jj*2][0]=t[0]; bh[pb][jj*2][1]=t[1];
                    bh[pb][jj*2+1][0]=t[2]; bh[pb][jj*2+1][1]=t[3];
                    ldsm_x4(t, swz(sKL + subo, rowB, colB));
                    bl[pb][jj*2][0]=t[0]; bl[pb][jj*2][1]=t[1];
                    bl[pb][jj*2+1][0]=t[2]; bl[pb][jj*2+1][1]=t[3];
                }
            };
            loadS(0, 0);
#pragma unroll
            for (int ks = 0; ks < 8; ++ks) {
                const int cur = ks & 1;
                if (ks < 7) loadS(ks + 1, cur ^ 1);
#pragma unroll
                for (int j = 0; j < 4; ++j) {
                    mma16816(s[j], ah[cur], bh[cur][j]);
                    mma16816(s[j], ah[cur], bl[cur][j]);
                    mma16816(s[j], al[cur], bh[cur][j]);
                }
            }
#pragma unroll
            for (int j = 0; j < 4; ++j) {
                const int row0 = wq*16 + (lane >> 2);
                const int cc = wk*32 + j*8 + (lane & 3)*2;
                *(float2*)&Ss[row0*68 + cc]     = make_float2(s[j][0]*scl, s[j][1]*scl);
                *(float2*)&Ss[(row0+8)*68 + cc] = make_float2(s[j][2]*scl, s[j][3]*scl);
            }
        }
        __syncthreads();
        // ---- softmax (fp32) + write P splits ----
        {
            const int k0 = kt * 64;
            float* row = Ss + sr*68;
            int kmax = q0 + sr - k0 + 1;
            if (kmax > 64) kmax = 64;
            const float m_old = m_s[sr];
            float mx = m_old;
#pragma unroll
            for (int c0 = 0; c0 < 16; ++c0) {
                const int c = sq*16 + c0;
                if (c < kmax) mx = fmaxf(mx, row[c]);
            }
            mx = fmaxf(mx, __shfl_xor_sync(0xffffffff, mx, 1));
            mx = fmaxf(mx, __shfl_xor_sync(0xffffffff, mx, 2));
            float sum = 0.0f;
#pragma unroll
            for (int cp = 0; cp < 8; ++cp) {
                const int c = sq*16 + cp*2;
                const float p0 = (c   < kmax) ? __expf(row[c]   - mx) : 0.0f;
                const float p1 = (c+1 < kmax) ? __expf(row[c+1] - mx) : 0.0f;
                sum += p0 + p1;
                __nv_bfloat16 h0, l0, h1, l1;
                bsplit(p0, h0, l0); bsplit(p1, h1, l1);
                const int colb = c*2;
                *(uint32_t*)(dyn_smem + swz(APH_OFF, sr, colb)) = pack_bf2(h0, h1);
                *(uint32_t*)(dyn_smem + swz(APL_OFF, sr, colb)) = pack_bf2(l0, l1);
            }
            sum += __shfl_xor_sync(0xffffffff, sum, 1);
            sum += __shfl_xor_sync(0xffffffff, sum, 2);
            if (sq == 0) {
                const float sc = __expf(m_old - mx);
                m_s[sr]  = mx;
                l_s[sr]  = l_s[sr] * sc + sum;
                sc_s[sr] = sc;
            }
        }
        __syncthreads();
        // ---- O = O*sc + P V (3-split, register-pipelined) ----
        {
            const int row0 = wq*16 + (lane >> 2);
            const float sc0 = sc_s[row0], sc1 = sc_s[row0 + 8];
#pragma unroll
            for (int j = 0; j < 8; ++j) {
                acc[j][0] *= sc0; acc[j][1] *= sc0;
                acc[j][2] *= sc1; acc[j][3] *= sc1;
            }
            uint32_t pah[2][4], pal[2][4], vbh[2][8][2], vbl[2][8][2];
            auto loadPV = [&](int ks, int pb) {
                const int colA = ks*32 + (g>>1)*16;
                const int colB = ks*32 + (g&1)*16;
                const int rowA = wq*16 + r + (g&1)*8;
                ldsm_x4(pah[pb], swz(sb + APH_OFF, rowA, colA));
                ldsm_x4(pal[pb], swz(sb + APL_OFF, rowA, colA));
#pragma unroll
                for (int jj = 0; jj < 4; ++jj) {
                    const int rowB = wk*64 + jj*16 + r + (g>>1)*8;
                    uint32_t t[4];
                    ldsm_x4(t, swz(sVH, rowB, colB));
                    vbh[pb][jj*2][0]=t[0]; vbh[pb][jj*2][1]=t[1];
                    vbh[pb][jj*2+1][0]=t[2]; vbh[pb][jj*2+1][1]=t[3];
                    ldsm_x4(t, swz(sVL, rowB, colB));
                    vbl[pb][jj*2][0]=t[0]; vbl[pb][jj*2][1]=t[1];
                    vbl[pb][jj*2+1][0]=t[2]; vbl[pb][jj*2+1][1]=t[3];
                }
            };
            loadPV(0, 0);
#pragma unroll
            for (int ks = 0; ks < 4; ++ks) {
                const int cur = ks & 1;
                if (ks < 3) loadPV(ks + 1, cur ^ 1);
#pragma unroll
                for (int j = 0; j < 8; ++j) {
                    mma16816(acc[j], pah[cur], vbh[cur][j]);
                    mma16816(acc[j], pah[cur], vbl[cur][j]);
                    mma16816(acc[j], pal[cur], vbh[cur][j]);
                }
            }
        }
        if (kt < qt) cp_wait0();
        __syncthreads();
    }

    // epilogue: normalize + split to bf16 hi/lo, reference layout
    {
        const int row0 = wq*16 + (lane >> 2);
        const float inv0 = 1.0f / l_s[row0];
        const float inv1 = 1.0f / l_s[row0 + 8];
        const int t0 = q0 + row0, t1 = t0 + 8;
        const int rowA = 128*h + (t0 >> 4), rowB2 = 128*h + (t1 >> 4);
        const int cbase0 = ((t0 & 15) << 7), cbase1 = ((t1 & 15) << 7);
#pragma unroll
        for (int j = 0; j < 8; ++j) {
            const int d = wk*64 + j*8 + (lane & 3)*2;
            const size_t i0 = (size_t)(b*T_ + rowA)*C_ + cbase0 + d;
            const size_t i1 = (size_t)(b*T_ + rowB2)*C_ + cbase1 + d;
            __nv_bfloat16 h0, l0, h1, l1;
            bsplit(acc[j][0]*inv0, h0, l0); bsplit(acc[j][1]*inv0, h1, l1);
            *(uint32_t*)&g_ah[i0] = pack_bf2(h0, h1);
            *(uint32_t*)&g_al[i0] = pack_bf2(l0, l1);
            bsplit(acc[j][2]*inv1, h0, l0); bsplit(acc[j][3]*inv1, h1, l1);
            *(uint32_t*)&g_ah[i1] = pack_bf2(h0, h1);
            *(uint32_t*)&g_al[i1] = pack_bf2(l0, l1);
        }
    }
}

// ---------------------------------------------------------------------------
extern "C" void kernel_launch(void* const* d_in, const int* in_sizes, int n_in,
                              void* d_out, int out_size)
{
    const float* x = nullptr; const float* qkv_w = nullptr; const float* out_w = nullptr;
    for (int i = 0; i < n_in; ++i) {
        if      (in_sizes[i] == B_*T_*C_) x     = (const float*)d_in[i];
        else if (in_sizes[i] == 3*C_*C_)  qkv_w = (const float*)d_in[i];
        else if (in_sizes[i] == C_*C_)    out_w = (const float*)d_in[i];
    }
    if (!x)     x     = (const float*)d_in[0];
    if (!qkv_w) qkv_w = (const float*)d_in[1];
    if (!out_w) out_w = (const float*)d_in[2];
    float* out = (float*)d_out;

    float *qkv_ptr;
    __nv_bfloat16 *xh, *xl, *wh, *wl, *oh, *ol, *ah, *al;
    cudaGetSymbolAddress((void**)&qkv_ptr,  g_qkv);
    cudaGetSymbolAddress((void**)&xh, g_xh); cudaGetSymbolAddress((void**)&xl, g_xl);
    cudaGetSymbolAddress((void**)&wh, g_wh); cudaGetSymbolAddress((void**)&wl, g_wl);
    cudaGetSymbolAddress((void**)&oh, g_oh); cudaGetSymbolAddress((void**)&ol, g_ol);
    cudaGetSymbolAddress((void**)&ah, g_ah); cudaGetSymbolAddress((void**)&al, g_al);

    cudaFuncSetAttribute(tc_gemm, cudaFuncAttributeMaxDynamicSharedMemorySize, TC_SMEM);
    cudaFuncSetAttribute(attn_kernel, cudaFuncAttributeMaxDynamicSharedMemorySize, ATT_SMEM);

    // 1) fp32 -> bf16 hi/lo splits
    split_bf16<<<(M_*C_/4 + 255)/256, 256>>>(x, xh, xl, M_*C_/4);
    split_bf16<<<(NQKV_*C_/4 + 255)/256, 256>>>(qkv_w, wh, wl, NQKV_*C_/4);
    split_bf16<<<(C_*C_/4 + 255)/256, 256>>>(out_w, oh, ol, C_*C_/4);
    // 2) QKV projection (HMMA, pipelined)
    tc_gemm<<<dim3(NQKV_/128, M_/128), 256, TC_SMEM>>>(xh, xl, wh, wl, qkv_ptr, NQKV_);
    // 3) RoPE + reorganize -> bf16 split operands
    rope_reorg<<<(B_*H_*64*(T_/4))/256, 256>>>();
    // 4) HMMA causal flash attention (writes g_ah/g_al directly)
    attn_kernel<<<dim3(T_/64, H_, B_), 256, ATT_SMEM>>>();
    // 5) Output projection (HMMA)
    tc_gemm<<<dim3(C_/128, M_/128), 256, TC_SMEM>>>(ah, al, oh, ol, out, C_);
}